// round 2
// baseline (speedup 1.0000x reference)
#include <cuda_runtime.h>
#include <math.h>

#define NLAYER 4
#define BB 2
#define TT 2048
#define CC 512
#define NH 8
#define HDIM 64
#define FF 2048
#define VOCAB 32000
#define MT (BB*TT)   // 4096 rows

// ---------------- scratch (device globals; no allocations allowed) ----------
__device__ float g_x   [(size_t)MT*CC];          // residual stream
__device__ float g_ln  [(size_t)MT*CC];          // layernorm output
__device__ float g_q   [(size_t)MT*CC];
__device__ float g_k   [(size_t)MT*CC];
__device__ float g_v   [(size_t)MT*CC];
__device__ float g_attn[(size_t)MT*CC];
__device__ float g_ff  [(size_t)MT*FF];
__device__ float g_scores[(size_t)BB*NH*TT*TT];  // 256 MB

// ---------------- embedding + positional ------------------------------------
__global__ void embed_kernel(const int* __restrict__ x,
                             const float* __restrict__ emb,
                             const float* __restrict__ pos,
                             float* __restrict__ out) {
    int idx = blockIdx.x * blockDim.x + threadIdx.x;
    if (idx >= MT * CC) return;
    int c  = idx % CC;
    int bt = idx / CC;
    int t  = bt % TT;
    int tok = x[bt];
    if (tok < 0) tok = 0;
    if (tok >= VOCAB) tok = VOCAB - 1;
    out[idx] = emb[(size_t)tok * CC + c] + pos[(size_t)t * CC + c];
}

// ---------------- layernorm (one block per row of length CC) ----------------
__global__ void ln_kernel(const float* __restrict__ in,
                          const float* __restrict__ g,
                          const float* __restrict__ b,
                          float* __restrict__ out) {
    int row = blockIdx.x;
    const float* xr = in + (size_t)row * CC;
    __shared__ float red[256];
    int tid = threadIdx.x;

    float s = 0.f;
    for (int i = tid; i < CC; i += 256) s += xr[i];
    red[tid] = s; __syncthreads();
    for (int o = 128; o > 0; o >>= 1) { if (tid < o) red[tid] += red[tid + o]; __syncthreads(); }
    float mean = red[0] * (1.0f / CC);
    __syncthreads();

    float vs = 0.f;
    for (int i = tid; i < CC; i += 256) { float d = xr[i] - mean; vs += d * d; }
    red[tid] = vs; __syncthreads();
    for (int o = 128; o > 0; o >>= 1) { if (tid < o) red[tid] += red[tid + o]; __syncthreads(); }
    float rstd = rsqrtf(red[0] * (1.0f / CC) + 1e-5f);

    for (int i = tid; i < CC; i += 256)
        out[(size_t)row * CC + i] = (xr[i] - mean) * rstd * g[i] + b[i];
}

// ---------------- generic GEMM: out[M,N] = A[M,K] * W[N,K]^T + bias ---------
// optional relu on (sum+bias), optional residual add afterwards.
// All of M,N divisible by 64; K divisible by 16.
__global__ void gemm_nt(const float* __restrict__ A,
                        const float* __restrict__ W,
                        const float* __restrict__ bias,
                        const float* __restrict__ residual,
                        float* __restrict__ out,
                        int M, int N, int K, int relu) {
    __shared__ float As[64][17];
    __shared__ float Ws[64][17];
    int tid = threadIdx.x;
    int tx = tid & 15, ty = tid >> 4;
    int row0 = blockIdx.y * 64, col0 = blockIdx.x * 64;
    const float* Ab = A + (size_t)row0 * K;
    const float* Wb = W + (size_t)col0 * K;
    float acc[4][4] = {};

    for (int k0 = 0; k0 < K; k0 += 16) {
#pragma unroll
        for (int i = 0; i < 4; i++) {
            int e = tid + i * 256;
            int r = e >> 4, c = e & 15;
            As[r][c] = Ab[(size_t)r * K + k0 + c];
            Ws[r][c] = Wb[(size_t)r * K + k0 + c];
        }
        __syncthreads();
#pragma unroll
        for (int kk = 0; kk < 16; kk++) {
            float a[4], w[4];
#pragma unroll
            for (int i = 0; i < 4; i++) a[i] = As[ty * 4 + i][kk];
#pragma unroll
            for (int j = 0; j < 4; j++) w[j] = Ws[tx * 4 + j][kk];
#pragma unroll
            for (int i = 0; i < 4; i++)
#pragma unroll
                for (int j = 0; j < 4; j++) acc[i][j] += a[i] * w[j];
        }
        __syncthreads();
    }

#pragma unroll
    for (int i = 0; i < 4; i++)
#pragma unroll
        for (int j = 0; j < 4; j++) {
            int m = row0 + ty * 4 + i, n = col0 + tx * 4 + j;
            float v = acc[i][j] + bias[n];
            if (relu) v = fmaxf(v, 0.f);
            if (residual) v += residual[(size_t)m * N + n];
            out[(size_t)m * N + n] = v;
        }
}

// ---------------- attention scores: S = Q K^T / sqrt(hd), batched over B*H --
__global__ void scores_kernel(const float* __restrict__ q,
                              const float* __restrict__ kmat,
                              float* __restrict__ scores) {
    int bh = blockIdx.z;
    int b = bh >> 3, h = bh & 7;
    const float* Q  = q    + (size_t)b * TT * CC + h * HDIM;
    const float* Kp = kmat + (size_t)b * TT * CC + h * HDIM;
    float* S = scores + (size_t)bh * TT * TT;

    __shared__ float Qs[64][17];
    __shared__ float Ks[64][17];
    int tid = threadIdx.x;
    int tx = tid & 15, ty = tid >> 4;
    int row0 = blockIdx.y * 64, col0 = blockIdx.x * 64;
    float acc[4][4] = {};

    for (int k0 = 0; k0 < HDIM; k0 += 16) {
#pragma unroll
        for (int i = 0; i < 4; i++) {
            int e = tid + i * 256;
            int r = e >> 4, c = e & 15;
            Qs[r][c] = Q [(size_t)(row0 + r) * CC + k0 + c];
            Ks[r][c] = Kp[(size_t)(col0 + r) * CC + k0 + c];
        }
        __syncthreads();
#pragma unroll
        for (int kk = 0; kk < 16; kk++) {
            float a[4], w[4];
#pragma unroll
            for (int i = 0; i < 4; i++) a[i] = Qs[ty * 4 + i][kk];
#pragma unroll
            for (int j = 0; j < 4; j++) w[j] = Ks[tx * 4 + j][kk];
#pragma unroll
            for (int i = 0; i < 4; i++)
#pragma unroll
                for (int j = 0; j < 4; j++) acc[i][j] += a[i] * w[j];
        }
        __syncthreads();
    }

#pragma unroll
    for (int i = 0; i < 4; i++)
#pragma unroll
        for (int j = 0; j < 4; j++)
            S[(size_t)(row0 + ty * 4 + i) * TT + col0 + tx * 4 + j] = acc[i][j] * 0.125f;
}

// ---------------- row softmax over T in place --------------------------------
__global__ void softmax_kernel(float* __restrict__ scores) {
    float* S = scores + (size_t)blockIdx.x * TT;
    __shared__ float red[256];
    int tid = threadIdx.x;

    float mx = -3.4e38f;
    for (int i = tid; i < TT; i += 256) mx = fmaxf(mx, S[i]);
    red[tid] = mx; __syncthreads();
    for (int o = 128; o > 0; o >>= 1) { if (tid < o) red[tid] = fmaxf(red[tid], red[tid + o]); __syncthreads(); }
    mx = red[0]; __syncthreads();

    float sum = 0.f;
    for (int i = tid; i < TT; i += 256) { float e = __expf(S[i] - mx); S[i] = e; sum += e; }
    red[tid] = sum; __syncthreads();
    for (int o = 128; o > 0; o >>= 1) { if (tid < o) red[tid] += red[tid + o]; __syncthreads(); }
    float inv = 1.0f / red[0];

    for (int i = tid; i < TT; i += 256) S[i] *= inv;
}

// ---------------- head-average of probs -> attn map output ------------------
__global__ void avg_attn_kernel(const float* __restrict__ scores,
                                float* __restrict__ out) {
    size_t idx = (size_t)blockIdx.x * blockDim.x + threadIdx.x;
    if (idx >= (size_t)BB * TT * TT) return;
    size_t b  = idx / ((size_t)TT * TT);
    size_t ts = idx % ((size_t)TT * TT);
    float s = 0.f;
#pragma unroll
    for (int h = 0; h < NH; h++)
        s += scores[(b * NH + h) * (size_t)TT * TT + ts];
    out[idx] = s * (1.0f / NH);
}

// ---------------- O = P V, batched over B*H; writes [B,T,C] layout ----------
__global__ void attnv_kernel(const float* __restrict__ probs,
                             const float* __restrict__ v,
                             float* __restrict__ attn) {
    int bh = blockIdx.z;
    int b = bh >> 3, h = bh & 7;
    const float* P = probs + (size_t)bh * TT * TT;
    const float* V = v    + (size_t)b * TT * CC + h * HDIM;
    float* O       = attn + (size_t)b * TT * CC + h * HDIM;

    __shared__ float Ps[64][17];
    __shared__ float Vs[16][65];
    int tid = threadIdx.x;
    int tx = tid & 15, ty = tid >> 4;
    int row0 = blockIdx.y * 64;
    float acc[4][4] = {};

    for (int k0 = 0; k0 < TT; k0 += 16) {
#pragma unroll
        for (int i = 0; i < 4; i++) {
            int e = tid + i * 256;
            int r = e >> 4, c = e & 15;
            Ps[r][c] = P[(size_t)(row0 + r) * TT + k0 + c];
        }
#pragma unroll
        for (int i = 0; i < 4; i++) {
            int e = tid + i * 256;
            int r = e >> 6, c = e & 63;
            Vs[r][c] = V[(size_t)(k0 + r) * CC + c];
        }
        __syncthreads();
#pragma unroll
        for (int kk = 0; kk < 16; kk++) {
            float a[4], w[4];
#pragma unroll
            for (int i = 0; i < 4; i++) a[i] = Ps[ty * 4 + i][kk];
#pragma unroll
            for (int j = 0; j < 4; j++) w[j] = Vs[kk][tx * 4 + j];
#pragma unroll
            for (int i = 0; i < 4; i++)
#pragma unroll
                for (int j = 0; j < 4; j++) acc[i][j] += a[i] * w[j];
        }
        __syncthreads();
    }

#pragma unroll
    for (int i = 0; i < 4; i++)
#pragma unroll
        for (int j = 0; j < 4; j++)
            O[(size_t)(row0 + ty * 4 + i) * CC + tx * 4 + j] = acc[i][j];
}

// ---------------- final pooled output: mean over T of lnf(x) ----------------
__global__ void final_mean_kernel(const float* __restrict__ hln,
                                  float* __restrict__ out) {
    int bd = blockIdx.x;           // B*CC blocks
    int b = bd / CC, d = bd % CC;
    __shared__ float red[256];
    int tid = threadIdx.x;
    float s = 0.f;
    for (int t = tid; t < TT; t += 256)
        s += hln[((size_t)b * TT + t) * CC + d];
    red[tid] = s; __syncthreads();
    for (int o = 128; o > 0; o >>= 1) { if (tid < o) red[tid] += red[tid + o]; __syncthreads(); }
    if (tid == 0) out[bd] = red[0] * (1.0f / TT);
}

// ---------------- launch ------------------------------------------------------
extern "C" void kernel_launch(void* const* d_in, const int* in_sizes, int n_in,
                              void* d_out, int out_size) {
    const int* x      = (const int*)d_in[0];
    const float* emb  = (const float*)d_in[1];
    const float* pos  = (const float*)d_in[2];
    const float* Wq = (const float*)d_in[3],  *bq = (const float*)d_in[4];
    const float* Wk = (const float*)d_in[5],  *bk = (const float*)d_in[6];
    const float* Wv = (const float*)d_in[7],  *bv = (const float*)d_in[8];
    const float* Wo = (const float*)d_in[9],  *bo = (const float*)d_in[10];
    const float* W1 = (const float*)d_in[11], *b1 = (const float*)d_in[12];
    const float* W2 = (const float*)d_in[13], *b2 = (const float*)d_in[14];
    const float* ln1g = (const float*)d_in[15], *ln1b = (const float*)d_in[16];
    const float* ln2g = (const float*)d_in[17], *ln2b = (const float*)d_in[18];
    const float* lnfg = (const float*)d_in[19], *lnfb = (const float*)d_in[20];
    float* out = (float*)d_out;

    float *xb, *lnb, *qb, *kb, *vb, *ab, *fb, *sb;
    cudaGetSymbolAddress((void**)&xb,  g_x);
    cudaGetSymbolAddress((void**)&lnb, g_ln);
    cudaGetSymbolAddress((void**)&qb,  g_q);
    cudaGetSymbolAddress((void**)&kb,  g_k);
    cudaGetSymbolAddress((void**)&vb,  g_v);
    cudaGetSymbolAddress((void**)&ab,  g_attn);
    cudaGetSymbolAddress((void**)&fb,  g_ff);
    cudaGetSymbolAddress((void**)&sb,  g_scores);

    const size_t attn_elems = (size_t)NLAYER * BB * TT * TT;
    float* attn_out = out + ((size_t)out_size - attn_elems);

    embed_kernel<<<(MT * CC + 255) / 256, 256>>>(x, emb, pos, xb);

    for (int l = 0; l < NLAYER; l++) {
        const float* wq = Wq + (size_t)l * CC * CC;
        const float* wk = Wk + (size_t)l * CC * CC;
        const float* wv = Wv + (size_t)l * CC * CC;
        const float* wo = Wo + (size_t)l * CC * CC;
        const float* w1 = W1 + (size_t)l * FF * CC;
        const float* w2 = W2 + (size_t)l * CC * FF;

        ln_kernel<<<MT, 256>>>(xb, ln1g + (size_t)l * CC, ln1b + (size_t)l * CC, lnb);

        dim3 gp(CC / 64, MT / 64);
        gemm_nt<<<gp, 256>>>(lnb, wq, bq + (size_t)l * CC, nullptr, qb, MT, CC, CC, 0);
        gemm_nt<<<gp, 256>>>(lnb, wk, bk + (size_t)l * CC, nullptr, kb, MT, CC, CC, 0);
        gemm_nt<<<gp, 256>>>(lnb, wv, bv + (size_t)l * CC, nullptr, vb, MT, CC, CC, 0);

        dim3 gs(TT / 64, TT / 64, BB * NH);
        scores_kernel<<<gs, 256>>>(qb, kb, sb);

        softmax_kernel<<<BB * NH * TT, 256>>>(sb);

        avg_attn_kernel<<<(unsigned)(((size_t)BB * TT * TT + 255) / 256), 256>>>(
            sb, attn_out + (size_t)l * BB * TT * TT);

        dim3 ga(1, TT / 64, BB * NH);
        attnv_kernel<<<ga, 256>>>(sb, vb, ab);

        gemm_nt<<<gp, 256>>>(ab, wo, bo + (size_t)l * CC, xb, xb, MT, CC, CC, 0);

        ln_kernel<<<MT, 256>>>(xb, ln2g + (size_t)l * CC, ln2b + (size_t)l * CC, lnb);

        dim3 gf1(FF / 64, MT / 64);
        gemm_nt<<<gf1, 256>>>(lnb, w1, b1 + (size_t)l * FF, nullptr, fb, MT, FF, CC, 1);

        gemm_nt<<<gp, 256>>>(fb, w2, b2 + (size_t)l * CC, xb, xb, MT, CC, FF, 0);
    }

    ln_kernel<<<MT, 256>>>(xb, lnfg, lnfb, lnb);
    final_mean_kernel<<<BB * CC, 256>>>(lnb, out);
}

// round 3
// speedup vs baseline: 2.0928x; 2.0928x over previous
#include <cuda_runtime.h>
#include <math.h>
#include <stdint.h>

#define NLAYER 4
#define BB 2
#define TT 2048
#define CC 512
#define NH 8
#define HDIM 64
#define FF 2048
#define VOCAB 32000
#define MT (BB*TT)   // 4096 rows

// ---------------- scratch (device globals; no allocations allowed) ----------
__device__ float g_x   [(size_t)MT*CC];
__device__ float g_ln  [(size_t)MT*CC];
__device__ float g_q   [(size_t)MT*CC];
__device__ float g_k   [(size_t)MT*CC];
__device__ float g_v   [(size_t)MT*CC];
__device__ float g_attn[(size_t)MT*CC];
__device__ float g_ff  [(size_t)MT*FF];
__device__ float g_scores[(size_t)BB*NH*TT*TT];  // 256 MB

// ---------------- helpers ----------------------------------------------------
__device__ __forceinline__ uint32_t f2tf32(float x) {
    uint32_t u;
    asm("cvt.rna.tf32.f32 %0, %1;" : "=r"(u) : "f"(x));
    return u;
}

__device__ __forceinline__ void mma_tf32(float* c, const uint32_t* a, const uint32_t* b) {
    asm volatile(
        "mma.sync.aligned.m16n8k8.row.col.f32.tf32.tf32.f32 "
        "{%0,%1,%2,%3}, {%4,%5,%6,%7}, {%8,%9}, {%0,%1,%2,%3};"
        : "+f"(c[0]), "+f"(c[1]), "+f"(c[2]), "+f"(c[3])
        : "r"(a[0]), "r"(a[1]), "r"(a[2]), "r"(a[3]), "r"(b[0]), "r"(b[1]));
}

// ---------------- embedding + positional ------------------------------------
__global__ void embed_kernel(const int* __restrict__ x,
                             const float* __restrict__ emb,
                             const float* __restrict__ pos,
                             float* __restrict__ out) {
    int idx = blockIdx.x * blockDim.x + threadIdx.x;
    if (idx >= MT * CC) return;
    int c  = idx % CC;
    int bt = idx / CC;
    int t  = bt % TT;
    int tok = x[bt];
    if (tok < 0) tok = 0;
    if (tok >= VOCAB) tok = VOCAB - 1;
    out[idx] = emb[(size_t)tok * CC + c] + pos[(size_t)t * CC + c];
}

// ---------------- layernorm (one block per row of length CC) ----------------
__global__ void ln_kernel(const float* __restrict__ in,
                          const float* __restrict__ g,
                          const float* __restrict__ b,
                          float* __restrict__ out) {
    int row = blockIdx.x;
    const float* xr = in + (size_t)row * CC;
    __shared__ float red[256];
    int tid = threadIdx.x;

    float s = 0.f;
    for (int i = tid; i < CC; i += 256) s += xr[i];
    red[tid] = s; __syncthreads();
    for (int o = 128; o > 0; o >>= 1) { if (tid < o) red[tid] += red[tid + o]; __syncthreads(); }
    float mean = red[0] * (1.0f / CC);
    __syncthreads();

    float vs = 0.f;
    for (int i = tid; i < CC; i += 256) { float d = xr[i] - mean; vs += d * d; }
    red[tid] = vs; __syncthreads();
    for (int o = 128; o > 0; o >>= 1) { if (tid < o) red[tid] += red[tid + o]; __syncthreads(); }
    float rstd = rsqrtf(red[0] * (1.0f / CC) + 1e-5f);

    for (int i = tid; i < CC; i += 256)
        out[(size_t)row * CC + i] = (xr[i] - mean) * rstd * g[i] + b[i];
}

// ---------------- tensor-core TF32 GEMM --------------------------------------
// C[M,N] = A[M,K] * B^T (NT, B as W[N,K]) or A * B (NN, B as [K,N])
// Tile: BM=128, BN=64, BK=32. 256 threads = 8 warps in 4(M) x 2(N).
// Each warp: 32x32 via m16n8k8 tiles (2 m-tiles x 4 n-tiles).
// EPI: 0 = scale only, 1 = +bias, 2 = +bias+relu, 3 = +bias+residual
// Batched via blockIdx.z decomposed as (zb, zh) with zdiv heads.
template<int EPI, bool BNN>
__global__ void gemm_tc(const float* __restrict__ A, const float* __restrict__ B,
                        const float* __restrict__ bias, const float* __restrict__ res,
                        float* __restrict__ C,
                        int lda, int ldb, int ldc, int K, float scale, int zdiv,
                        long long sAb, long long sAh, long long sBb, long long sBh,
                        long long sCb, long long sCh) {
    __shared__ uint32_t As[128 * 33];
    __shared__ uint32_t Bs[64 * 33];

    int tid = threadIdx.x;
    int lane = tid & 31;
    int wid = tid >> 5;
    int warpM = wid & 3;          // 0..3, rows 32 each
    int warpN = wid >> 2;         // 0..1, cols 32 each
    int grp = lane >> 2;          // 0..7
    int qd  = lane & 3;           // 0..3

    int z = blockIdx.z;
    int zb = z / zdiv, zh = z % zdiv;
    A += zb * sAb + zh * sAh;
    B += zb * sBb + zh * sBh;
    C += zb * sCb + zh * sCh;

    int row0 = blockIdx.y * 128;
    int col0 = blockIdx.x * 64;

    float acc[2][4][4];
#pragma unroll
    for (int mt = 0; mt < 2; mt++)
#pragma unroll
        for (int nt = 0; nt < 4; nt++)
#pragma unroll
            for (int i = 0; i < 4; i++) acc[mt][nt][i] = 0.f;

    for (int k0 = 0; k0 < K; k0 += 32) {
        // ---- load A tile: 128x32 (1024 float4, 4 per thread) ----
#pragma unroll
        for (int i = 0; i < 4; i++) {
            int j = i * 256 + tid;
            int r = j >> 3, c4 = (j & 7) * 4;
            float4 v = *(const float4*)(A + (size_t)(row0 + r) * lda + k0 + c4);
            As[r * 33 + c4 + 0] = f2tf32(v.x);
            As[r * 33 + c4 + 1] = f2tf32(v.y);
            As[r * 33 + c4 + 2] = f2tf32(v.z);
            As[r * 33 + c4 + 3] = f2tf32(v.w);
        }
        // ---- load B tile into Bs[n][k] (64x32) ----
        if (!BNN) {
            // B = W[N,K]: Bs[n][k] = W[(col0+n)*ldb + k0+k]
#pragma unroll
            for (int i = 0; i < 2; i++) {
                int j = i * 256 + tid;
                int r = j >> 3, c4 = (j & 7) * 4;
                float4 v = *(const float4*)(B + (size_t)(col0 + r) * ldb + k0 + c4);
                Bs[r * 33 + c4 + 0] = f2tf32(v.x);
                Bs[r * 33 + c4 + 1] = f2tf32(v.y);
                Bs[r * 33 + c4 + 2] = f2tf32(v.z);
                Bs[r * 33 + c4 + 3] = f2tf32(v.w);
            }
        } else {
            // B = V[K,N]: Bs[n][k] = V[(k0+k)*ldb + col0+n]
#pragma unroll
            for (int i = 0; i < 2; i++) {
                int j = i * 256 + tid;           // 512 float4 jobs: 32 k-rows x 16 n-quads
                int k = j >> 4, n4 = (j & 15) * 4;
                float4 v = *(const float4*)(B + (size_t)(k0 + k) * ldb + col0 + n4);
                Bs[(n4 + 0) * 33 + k] = f2tf32(v.x);
                Bs[(n4 + 1) * 33 + k] = f2tf32(v.y);
                Bs[(n4 + 2) * 33 + k] = f2tf32(v.z);
                Bs[(n4 + 3) * 33 + k] = f2tf32(v.w);
            }
        }
        __syncthreads();

#pragma unroll
        for (int kt = 0; kt < 4; kt++) {
            uint32_t afr[2][4];
#pragma unroll
            for (int mt = 0; mt < 2; mt++) {
                int r0 = warpM * 32 + mt * 16 + grp;
                afr[mt][0] = As[(r0)     * 33 + kt * 8 + qd];
                afr[mt][1] = As[(r0 + 8) * 33 + kt * 8 + qd];
                afr[mt][2] = As[(r0)     * 33 + kt * 8 + qd + 4];
                afr[mt][3] = As[(r0 + 8) * 33 + kt * 8 + qd + 4];
            }
            uint32_t bfr[4][2];
#pragma unroll
            for (int nt = 0; nt < 4; nt++) {
                int nb = warpN * 32 + nt * 8 + grp;
                bfr[nt][0] = Bs[nb * 33 + kt * 8 + qd];
                bfr[nt][1] = Bs[nb * 33 + kt * 8 + qd + 4];
            }
#pragma unroll
            for (int mt = 0; mt < 2; mt++)
#pragma unroll
                for (int nt = 0; nt < 4; nt++)
                    mma_tf32(acc[mt][nt], afr[mt], bfr[nt]);
        }
        __syncthreads();
    }

    // ---- epilogue ----
#pragma unroll
    for (int mt = 0; mt < 2; mt++) {
#pragma unroll
        for (int nt = 0; nt < 4; nt++) {
            int row = row0 + warpM * 32 + mt * 16 + grp;
            int col = col0 + warpN * 32 + nt * 8 + qd * 2;
#pragma unroll
            for (int half = 0; half < 2; half++) {
                int r = row + half * 8;
                float v0 = acc[mt][nt][half * 2 + 0];
                float v1 = acc[mt][nt][half * 2 + 1];
                if (EPI == 0) { v0 *= scale; v1 *= scale; }
                if (EPI >= 1) { v0 += bias[col]; v1 += bias[col + 1]; }
                if (EPI == 2) { v0 = fmaxf(v0, 0.f); v1 = fmaxf(v1, 0.f); }
                if (EPI == 3) {
                    v0 += res[(size_t)r * ldc + col];
                    v1 += res[(size_t)r * ldc + col + 1];
                }
                *(float2*)(C + (size_t)r * ldc + col) = make_float2(v0, v1);
            }
        }
    }
}

// ---------------- fused softmax (8 heads) + head-average --------------------
// grid: (TT, BB); block 256. Row t of batch b for all 8 heads.
__global__ void softmax_avg_kernel(float* __restrict__ scores,
                                   float* __restrict__ avg) {
    int t = blockIdx.x, b = blockIdx.y, tid = threadIdx.x;
    __shared__ float red[256];
    float4 acc0 = make_float4(0, 0, 0, 0), acc1 = make_float4(0, 0, 0, 0);

#pragma unroll
    for (int h = 0; h < NH; h++) {
        float4* S = (float4*)(scores + ((size_t)(b * NH + h) * TT + t) * TT);
        float4 v0 = S[tid], v1 = S[tid + 256];

        float m = fmaxf(fmaxf(fmaxf(v0.x, v0.y), fmaxf(v0.z, v0.w)),
                        fmaxf(fmaxf(v1.x, v1.y), fmaxf(v1.z, v1.w)));
        red[tid] = m; __syncthreads();
        for (int o = 128; o > 0; o >>= 1) { if (tid < o) red[tid] = fmaxf(red[tid], red[tid + o]); __syncthreads(); }
        m = red[0]; __syncthreads();

        v0.x = __expf(v0.x - m); v0.y = __expf(v0.y - m);
        v0.z = __expf(v0.z - m); v0.w = __expf(v0.w - m);
        v1.x = __expf(v1.x - m); v1.y = __expf(v1.y - m);
        v1.z = __expf(v1.z - m); v1.w = __expf(v1.w - m);
        float s = v0.x + v0.y + v0.z + v0.w + v1.x + v1.y + v1.z + v1.w;
        red[tid] = s; __syncthreads();
        for (int o = 128; o > 0; o >>= 1) { if (tid < o) red[tid] += red[tid + o]; __syncthreads(); }
        float inv = 1.0f / red[0]; __syncthreads();

        v0.x *= inv; v0.y *= inv; v0.z *= inv; v0.w *= inv;
        v1.x *= inv; v1.y *= inv; v1.z *= inv; v1.w *= inv;
        S[tid] = v0; S[tid + 256] = v1;
        acc0.x += v0.x; acc0.y += v0.y; acc0.z += v0.z; acc0.w += v0.w;
        acc1.x += v1.x; acc1.y += v1.y; acc1.z += v1.z; acc1.w += v1.w;
    }

    const float inv8 = 1.0f / NH;
    acc0.x *= inv8; acc0.y *= inv8; acc0.z *= inv8; acc0.w *= inv8;
    acc1.x *= inv8; acc1.y *= inv8; acc1.z *= inv8; acc1.w *= inv8;
    float4* O = (float4*)(avg + ((size_t)b * TT + t) * TT);
    O[tid] = acc0; O[tid + 256] = acc1;
}

// ---------------- final pooled output: mean over T of lnf(x) ----------------
__global__ void final_mean_kernel(const float* __restrict__ hln,
                                  float* __restrict__ out) {
    int bd = blockIdx.x;
    int b = bd / CC, d = bd % CC;
    __shared__ float red[256];
    int tid = threadIdx.x;
    float s = 0.f;
    for (int t = tid; t < TT; t += 256)
        s += hln[((size_t)b * TT + t) * CC + d];
    red[tid] = s; __syncthreads();
    for (int o = 128; o > 0; o >>= 1) { if (tid < o) red[tid] += red[tid + o]; __syncthreads(); }
    if (tid == 0) out[bd] = red[0] * (1.0f / TT);
}

// ---------------- launch ------------------------------------------------------
extern "C" void kernel_launch(void* const* d_in, const int* in_sizes, int n_in,
                              void* d_out, int out_size) {
    const int* x      = (const int*)d_in[0];
    const float* emb  = (const float*)d_in[1];
    const float* pos  = (const float*)d_in[2];
    const float* Wq = (const float*)d_in[3],  *bq = (const float*)d_in[4];
    const float* Wk = (const float*)d_in[5],  *bk = (const float*)d_in[6];
    const float* Wv = (const float*)d_in[7],  *bv = (const float*)d_in[8];
    const float* Wo = (const float*)d_in[9],  *bo = (const float*)d_in[10];
    const float* W1 = (const float*)d_in[11], *b1 = (const float*)d_in[12];
    const float* W2 = (const float*)d_in[13], *b2 = (const float*)d_in[14];
    const float* ln1g = (const float*)d_in[15], *ln1b = (const float*)d_in[16];
    const float* ln2g = (const float*)d_in[17], *ln2b = (const float*)d_in[18];
    const float* lnfg = (const float*)d_in[19], *lnfb = (const float*)d_in[20];
    float* out = (float*)d_out;

    float *xb, *lnb, *qb, *kb, *vb, *ab, *fb, *sb;
    cudaGetSymbolAddress((void**)&xb,  g_x);
    cudaGetSymbolAddress((void**)&lnb, g_ln);
    cudaGetSymbolAddress((void**)&qb,  g_q);
    cudaGetSymbolAddress((void**)&kb,  g_k);
    cudaGetSymbolAddress((void**)&vb,  g_v);
    cudaGetSymbolAddress((void**)&ab,  g_attn);
    cudaGetSymbolAddress((void**)&fb,  g_ff);
    cudaGetSymbolAddress((void**)&sb,  g_scores);

    const size_t attn_elems = (size_t)NLAYER * BB * TT * TT;
    float* attn_out = out + ((size_t)out_size - attn_elems);

    embed_kernel<<<(MT * CC + 255) / 256, 256>>>(x, emb, pos, xb);

    const long long LTT2 = (long long)TT * TT;
    const long long LTC  = (long long)TT * CC;

    for (int l = 0; l < NLAYER; l++) {
        const float* wq = Wq + (size_t)l * CC * CC;
        const float* wk = Wk + (size_t)l * CC * CC;
        const float* wv = Wv + (size_t)l * CC * CC;
        const float* wo = Wo + (size_t)l * CC * CC;
        const float* w1 = W1 + (size_t)l * FF * CC;
        const float* w2 = W2 + (size_t)l * CC * FF;

        ln_kernel<<<MT, 256>>>(xb, ln1g + (size_t)l * CC, ln1b + (size_t)l * CC, lnb);

        dim3 gp(CC / 64, MT / 128);
        gemm_tc<1, false><<<gp, 256>>>(lnb, wq, bq + (size_t)l * CC, nullptr, qb,
                                       CC, CC, CC, CC, 1.f, 1, 0, 0, 0, 0, 0, 0);
        gemm_tc<1, false><<<gp, 256>>>(lnb, wk, bk + (size_t)l * CC, nullptr, kb,
                                       CC, CC, CC, CC, 1.f, 1, 0, 0, 0, 0, 0, 0);
        gemm_tc<1, false><<<gp, 256>>>(lnb, wv, bv + (size_t)l * CC, nullptr, vb,
                                       CC, CC, CC, CC, 1.f, 1, 0, 0, 0, 0, 0, 0);

        // scores: S = Q K^T / 8   [per b,h]  M=T, N=T, K=64
        dim3 gs(TT / 64, TT / 128, BB * NH);
        gemm_tc<0, false><<<gs, 256>>>(qb, kb, nullptr, nullptr, sb,
                                       CC, CC, TT, HDIM, 0.125f, NH,
                                       LTC, 64, LTC, 64, (long long)NH * LTT2, LTT2);

        dim3 gsm(TT, BB);
        softmax_avg_kernel<<<gsm, 256>>>(sb, attn_out + (size_t)l * BB * TT * TT);

        // attnv: O = P V  [per b,h]  M=T, N=64, K=T  (B is NN: V[K=T, N via CC stride])
        dim3 ga(1, TT / 128, BB * NH);
        gemm_tc<0, true><<<ga, 256>>>(sb, vb, nullptr, nullptr, ab,
                                      TT, CC, CC, TT, 1.f, NH,
                                      (long long)NH * LTT2, LTT2, LTC, 64, LTC, 64);

        gemm_tc<3, false><<<gp, 256>>>(ab, wo, bo + (size_t)l * CC, xb, xb,
                                       CC, CC, CC, CC, 1.f, 1, 0, 0, 0, 0, 0, 0);

        ln_kernel<<<MT, 256>>>(xb, ln2g + (size_t)l * CC, ln2b + (size_t)l * CC, lnb);

        dim3 gf1(FF / 64, MT / 128);
        gemm_tc<2, false><<<gf1, 256>>>(lnb, w1, b1 + (size_t)l * FF, nullptr, fb,
                                        CC, CC, FF, CC, 1.f, 1, 0, 0, 0, 0, 0, 0);

        gemm_tc<3, false><<<gp, 256>>>(fb, w2, b2 + (size_t)l * CC, xb, xb,
                                       FF, FF, CC, FF, 1.f, 1, 0, 0, 0, 0, 0, 0);
    }

    ln_kernel<<<MT, 256>>>(xb, lnfg, lnfb, lnb);
    final_mean_kernel<<<BB * CC, 256>>>(lnb, out);
}

// round 4
// speedup vs baseline: 3.9809x; 1.9021x over previous
#include <cuda_runtime.h>
#include <math.h>
#include <stdint.h>

#define NLAYER 4
#define BB 2
#define TT 2048
#define CC 512
#define NH 8
#define HDIM 64
#define FF 2048
#define VOCAB 32000
#define MT (BB*TT)   // 4096 rows

// ---------------- scratch (device globals; no allocations allowed) ----------
__device__ float g_x   [(size_t)MT*CC];
__device__ float g_ln  [(size_t)MT*CC];
__device__ float g_q   [(size_t)MT*CC];
__device__ float g_k   [(size_t)MT*CC];
__device__ float g_v   [(size_t)MT*CC];
__device__ float g_attn[(size_t)MT*CC];
__device__ float g_ff  [(size_t)MT*FF];
__device__ float g_scores[(size_t)BB*NH*TT*TT];  // 256 MB

// ---------------- helpers ----------------------------------------------------
__device__ __forceinline__ uint32_t f2tf32(float x) {
    uint32_t u;
    asm("cvt.rna.tf32.f32 %0, %1;" : "=r"(u) : "f"(x));
    return u;
}

__device__ __forceinline__ void mma_tf32(float* c, const uint32_t* a, const uint32_t* b) {
    asm volatile(
        "mma.sync.aligned.m16n8k8.row.col.f32.tf32.tf32.f32 "
        "{%0,%1,%2,%3}, {%4,%5,%6,%7}, {%8,%9}, {%0,%1,%2,%3};"
        : "+f"(c[0]), "+f"(c[1]), "+f"(c[2]), "+f"(c[3])
        : "r"(a[0]), "r"(a[1]), "r"(a[2]), "r"(a[3]), "r"(b[0]), "r"(b[1]));
}

__device__ __forceinline__ void cp16(void* sdst, const void* gsrc) {
    unsigned s = (unsigned)__cvta_generic_to_shared(sdst);
    asm volatile("cp.async.cg.shared.global [%0], [%1], 16;\n" :: "r"(s), "l"(gsrc));
}
__device__ __forceinline__ void cp_commit() { asm volatile("cp.async.commit_group;\n"); }
template<int N>
__device__ __forceinline__ void cp_wait() { asm volatile("cp.async.wait_group %0;\n" :: "n"(N)); }

// =============================================================================
// TF32 tensor-core GEMM core. C[M,N] = A[M,K] @ B' where
//   BNN=false: B is W[N,K] (NT);  BNN=true: B is V[K,N] (NN).
// CTA tile BM x BN x 32, 256 threads, double-buffered cp.async pipeline.
// EPI: 0 = *scale, 1 = +bias, 2 = +bias,relu, 3 = +bias,+residual
// =============================================================================
template<int EPI, bool BNN, int BM, int BN>
__device__ __forceinline__ void gemm_core(
    const float* __restrict__ A, const float* __restrict__ B,
    const float* __restrict__ bias, const float* __restrict__ res,
    float* __restrict__ C, int lda, int ldb, int ldc, int K, float scale)
{
    constexpr int WM   = BM / 64;           // warps along M (1 or 2)
    constexpr int WN   = 8 / WM;            // warps along N
    constexpr int NCW  = BN / WN;           // cols per warp
    constexpr int NT_  = NCW / 8;           // 8-wide n tiles per warp
    constexpr int BROWS = BNN ? 32 : BN;
    constexpr int BSTR  = BNN ? (BN + 4) : 36;

    extern __shared__ float smem[];
    float* As = smem;                        // 2 * BM * 36
    float* Bs = smem + 2 * BM * 36;          // 2 * BROWS * BSTR

    const int tid  = threadIdx.x;
    const int lane = tid & 31, wid = tid >> 5;
    const int warpM = (WM == 1) ? 0 : (wid & 1);
    const int warpN = (WM == 1) ? wid : (wid >> 1);
    const int grp = lane >> 2, qd = lane & 3;

    const int row0 = blockIdx.y * BM;
    const int col0 = blockIdx.x * BN;

    float acc[4][NT_][4];
#pragma unroll
    for (int mt = 0; mt < 4; mt++)
#pragma unroll
        for (int nt = 0; nt < NT_; nt++)
#pragma unroll
            for (int i = 0; i < 4; i++) acc[mt][nt][i] = 0.f;

    auto loadA = [&](int buf, int k0) {
#pragma unroll
        for (int i = 0; i < BM / 32; i++) {
            int idx = i * 256 + tid;
            int r = idx >> 3, c4 = (idx & 7) << 2;
            cp16(As + buf * BM * 36 + r * 36 + c4,
                 A + (size_t)(row0 + r) * lda + k0 + c4);
        }
    };
    auto loadB = [&](int buf, int k0) {
        if (!BNN) {
#pragma unroll
            for (int i = 0; i < BN / 32; i++) {
                int idx = i * 256 + tid;
                int r = idx >> 3, c4 = (idx & 7) << 2;
                cp16(Bs + buf * BROWS * BSTR + r * BSTR + c4,
                     B + (size_t)(col0 + r) * ldb + k0 + c4);
            }
        } else {
#pragma unroll
            for (int i = 0; i < BN / 32; i++) {
                int idx = i * 256 + tid;
                int kk = idx / (BN / 4);
                int n4 = (idx % (BN / 4)) << 2;
                cp16(Bs + buf * BROWS * BSTR + kk * BSTR + n4,
                     B + (size_t)(k0 + kk) * ldb + col0 + n4);
            }
        }
    };

    auto compute = [&](int buf) {
        const float* Ab = As + buf * BM * 36;
        const float* Bb = Bs + buf * BROWS * BSTR;
#pragma unroll
        for (int kt = 0; kt < 4; kt++) {
            uint32_t af[4][4];
#pragma unroll
            for (int mt = 0; mt < 4; mt++) {
                int r0 = warpM * 64 + mt * 16 + grp;
                af[mt][0] = f2tf32(Ab[(r0)     * 36 + kt * 8 + qd]);
                af[mt][1] = f2tf32(Ab[(r0 + 8) * 36 + kt * 8 + qd]);
                af[mt][2] = f2tf32(Ab[(r0)     * 36 + kt * 8 + qd + 4]);
                af[mt][3] = f2tf32(Ab[(r0 + 8) * 36 + kt * 8 + qd + 4]);
            }
            uint32_t bf[NT_][2];
#pragma unroll
            for (int nt = 0; nt < NT_; nt++) {
                int nb = warpN * NCW + nt * 8 + grp;
                if (!BNN) {
                    bf[nt][0] = f2tf32(Bb[nb * BSTR + kt * 8 + qd]);
                    bf[nt][1] = f2tf32(Bb[nb * BSTR + kt * 8 + qd + 4]);
                } else {
                    bf[nt][0] = f2tf32(Bb[(kt * 8 + qd)     * BSTR + nb]);
                    bf[nt][1] = f2tf32(Bb[(kt * 8 + qd + 4) * BSTR + nb]);
                }
            }
#pragma unroll
            for (int mt = 0; mt < 4; mt++)
#pragma unroll
                for (int nt = 0; nt < NT_; nt++)
                    mma_tf32(acc[mt][nt], af[mt], bf[nt]);
        }
    };

    const int nk = K >> 5;               // K/32, always >= 2 here
    loadA(0, 0);  loadB(0, 0);  cp_commit();
    loadA(1, 32); loadB(1, 32); cp_commit();
    cp_wait<1>();
    __syncthreads();

    for (int kb = 0; kb < nk; kb++) {
        compute(kb & 1);
        __syncthreads();
        if (kb + 2 < nk) { loadA(kb & 1, (kb + 2) * 32); loadB(kb & 1, (kb + 2) * 32); }
        cp_commit();
        cp_wait<1>();
        __syncthreads();
    }

    // ---- epilogue ----
#pragma unroll
    for (int mt = 0; mt < 4; mt++)
#pragma unroll
        for (int nt = 0; nt < NT_; nt++) {
            int row = row0 + warpM * 64 + mt * 16 + grp;
            int col = col0 + warpN * NCW + nt * 8 + qd * 2;
#pragma unroll
            for (int half = 0; half < 2; half++) {
                int r = row + half * 8;
                float v0 = acc[mt][nt][half * 2 + 0];
                float v1 = acc[mt][nt][half * 2 + 1];
                if (EPI == 0) { v0 *= scale; v1 *= scale; }
                if (EPI >= 1) { v0 += bias[col]; v1 += bias[col + 1]; }
                if (EPI == 2) { v0 = fmaxf(v0, 0.f); v1 = fmaxf(v1, 0.f); }
                if (EPI == 3) {
                    v0 += res[(size_t)r * ldc + col];
                    v1 += res[(size_t)r * ldc + col + 1];
                }
                *(float2*)(C + (size_t)r * ldc + col) = make_float2(v0, v1);
            }
        }
}

// ---- generic batched wrapper ------------------------------------------------
template<int EPI, bool BNN, int BM, int BN>
__global__ void __launch_bounds__(256)
gemm_tc_kernel(const float* __restrict__ A, const float* __restrict__ B,
               const float* __restrict__ bias, const float* __restrict__ res,
               float* __restrict__ C,
               int lda, int ldb, int ldc, int K, float scale, int zdiv,
               long long sAb, long long sAh, long long sBb, long long sBh,
               long long sCb, long long sCh) {
    int z = blockIdx.z;
    int zb = z / zdiv, zh = z % zdiv;
    A += zb * sAb + zh * sAh;
    B += zb * sBb + zh * sBh;
    C += zb * sCb + zh * sCh;
    if (EPI == 3) res += zb * sCb + zh * sCh;
    gemm_core<EPI, BNN, BM, BN>(A, B, bias, res, C, lda, ldb, ldc, K, scale);
}

// ---- fused QKV (z selects weight/bias/output) --------------------------------
template<int BM, int BN>
__global__ void __launch_bounds__(256)
gemm_qkv_kernel(const float* __restrict__ A,
                const float* __restrict__ Wq, const float* __restrict__ Wk,
                const float* __restrict__ Wv,
                const float* __restrict__ bq, const float* __restrict__ bk,
                const float* __restrict__ bv,
                float* __restrict__ q, float* __restrict__ k, float* __restrict__ v) {
    int z = blockIdx.z;
    const float* B    = z == 0 ? Wq : (z == 1 ? Wk : Wv);
    const float* bias = z == 0 ? bq : (z == 1 ? bk : bv);
    float* C          = z == 0 ? q  : (z == 1 ? k  : v);
    gemm_core<1, false, BM, BN>(A, B, bias, nullptr, C, CC, CC, CC, CC, 1.f);
}

// ---------------- embedding + positional ------------------------------------
__global__ void embed_kernel(const int* __restrict__ x,
                             const float* __restrict__ emb,
                             const float* __restrict__ pos,
                             float* __restrict__ out) {
    int idx = blockIdx.x * blockDim.x + threadIdx.x;
    if (idx >= MT * CC) return;
    int c  = idx % CC;
    int bt = idx / CC;
    int t  = bt % TT;
    int tok = x[bt];
    if (tok < 0) tok = 0;
    if (tok >= VOCAB) tok = VOCAB - 1;
    out[idx] = emb[(size_t)tok * CC + c] + pos[(size_t)t * CC + c];
}

// ---------------- layernorm: one warp per 512-float row ----------------------
__global__ void ln_kernel(const float* __restrict__ in,
                          const float* __restrict__ g,
                          const float* __restrict__ b,
                          float* __restrict__ out) {
    int row  = blockIdx.x * 8 + (threadIdx.x >> 5);
    int lane = threadIdx.x & 31;
    const float4* xr = (const float4*)(in + (size_t)row * CC);
    float4 v[4];
    float s = 0.f;
#pragma unroll
    for (int i = 0; i < 4; i++) {
        v[i] = xr[i * 32 + lane];
        s += v[i].x + v[i].y + v[i].z + v[i].w;
    }
#pragma unroll
    for (int o = 16; o; o >>= 1) s += __shfl_xor_sync(0xffffffffu, s, o);
    float mean = s * (1.0f / CC);
    float var = 0.f;
#pragma unroll
    for (int i = 0; i < 4; i++) {
        float dx = v[i].x - mean, dy = v[i].y - mean, dz = v[i].z - mean, dw = v[i].w - mean;
        var += dx * dx + dy * dy + dz * dz + dw * dw;
    }
#pragma unroll
    for (int o = 16; o; o >>= 1) var += __shfl_xor_sync(0xffffffffu, var, o);
    float rstd = rsqrtf(var * (1.0f / CC) + 1e-5f);
    float4* op = (float4*)(out + (size_t)row * CC);
    const float4* gp = (const float4*)g;
    const float4* bp = (const float4*)b;
#pragma unroll
    for (int i = 0; i < 4; i++) {
        float4 gg = gp[i * 32 + lane], bb = bp[i * 32 + lane];
        float4 o4;
        o4.x = (v[i].x - mean) * rstd * gg.x + bb.x;
        o4.y = (v[i].y - mean) * rstd * gg.y + bb.y;
        o4.z = (v[i].z - mean) * rstd * gg.z + bb.z;
        o4.w = (v[i].w - mean) * rstd * gg.w + bb.w;
        op[i * 32 + lane] = o4;
    }
}

// ---------------- fused softmax (warp per head) + head-average ---------------
__global__ void __launch_bounds__(256)
softmax_avg_kernel(float* __restrict__ scores, float* __restrict__ avg) {
    __shared__ float sp[4][TT];          // 32 KB: 4 heads per staging round
    int t = blockIdx.x, b = blockIdx.y;
    int tid = threadIdx.x, lane = tid & 31, w = tid >> 5;

    float4* S = (float4*)(scores + ((size_t)(b * NH + w) * TT + t) * TT);
    float4 v[16];
    float m = -3.4e38f;
#pragma unroll
    for (int i = 0; i < 16; i++) {
        v[i] = S[i * 32 + lane];
        m = fmaxf(m, fmaxf(fmaxf(v[i].x, v[i].y), fmaxf(v[i].z, v[i].w)));
    }
#pragma unroll
    for (int o = 16; o; o >>= 1) m = fmaxf(m, __shfl_xor_sync(0xffffffffu, m, o));
    float s = 0.f;
#pragma unroll
    for (int i = 0; i < 16; i++) {
        v[i].x = __expf(v[i].x - m); v[i].y = __expf(v[i].y - m);
        v[i].z = __expf(v[i].z - m); v[i].w = __expf(v[i].w - m);
        s += v[i].x + v[i].y + v[i].z + v[i].w;
    }
#pragma unroll
    for (int o = 16; o; o >>= 1) s += __shfl_xor_sync(0xffffffffu, s, o);
    float inv = 1.0f / s;
#pragma unroll
    for (int i = 0; i < 16; i++) {
        v[i].x *= inv; v[i].y *= inv; v[i].z *= inv; v[i].w *= inv;
        S[i * 32 + lane] = v[i];
    }

    float4 a0 = make_float4(0, 0, 0, 0), a1 = make_float4(0, 0, 0, 0);
#pragma unroll
    for (int round = 0; round < 2; round++) {
        if ((w >> 2) == round) {
            float4* row = (float4*)sp[w & 3];
#pragma unroll
            for (int i = 0; i < 16; i++) row[i * 32 + lane] = v[i];
        }
        __syncthreads();
#pragma unroll
        for (int h = 0; h < 4; h++) {
            float4 p = ((float4*)sp[h])[tid];
            float4 q = ((float4*)sp[h])[tid + 256];
            a0.x += p.x; a0.y += p.y; a0.z += p.z; a0.w += p.w;
            a1.x += q.x; a1.y += q.y; a1.z += q.z; a1.w += q.w;
        }
        __syncthreads();
    }
    const float inv8 = 1.0f / NH;
    a0.x *= inv8; a0.y *= inv8; a0.z *= inv8; a0.w *= inv8;
    a1.x *= inv8; a1.y *= inv8; a1.z *= inv8; a1.w *= inv8;
    float4* O = (float4*)(avg + ((size_t)b * TT + t) * TT);
    O[tid] = a0; O[tid + 256] = a1;
}

// ---------------- final pooled output: mean over T of lnf(x) ----------------
__global__ void final_mean_kernel(const float* __restrict__ hln,
                                  float* __restrict__ out) {
    int bd = blockIdx.x;
    int b = bd / CC, d = bd % CC;
    __shared__ float red[256];
    int tid = threadIdx.x;
    float s = 0.f;
    for (int t = tid; t < TT; t += 256)
        s += hln[((size_t)b * TT + t) * CC + d];
    red[tid] = s; __syncthreads();
    for (int o = 128; o > 0; o >>= 1) { if (tid < o) red[tid] += red[tid + o]; __syncthreads(); }
    if (tid == 0) out[bd] = red[0] * (1.0f / TT);
}

// ---------------- launch ------------------------------------------------------
extern "C" void kernel_launch(void* const* d_in, const int* in_sizes, int n_in,
                              void* d_out, int out_size) {
    const int* x      = (const int*)d_in[0];
    const float* emb  = (const float*)d_in[1];
    const float* pos  = (const float*)d_in[2];
    const float* Wq = (const float*)d_in[3],  *bq = (const float*)d_in[4];
    const float* Wk = (const float*)d_in[5],  *bk = (const float*)d_in[6];
    const float* Wv = (const float*)d_in[7],  *bv = (const float*)d_in[8];
    const float* Wo = (const float*)d_in[9],  *bo = (const float*)d_in[10];
    const float* W1 = (const float*)d_in[11], *b1 = (const float*)d_in[12];
    const float* W2 = (const float*)d_in[13], *b2 = (const float*)d_in[14];
    const float* ln1g = (const float*)d_in[15], *ln1b = (const float*)d_in[16];
    const float* ln2g = (const float*)d_in[17], *ln2b = (const float*)d_in[18];
    const float* lnfg = (const float*)d_in[19], *lnfb = (const float*)d_in[20];
    float* out = (float*)d_out;

    float *xb, *lnb, *qb, *kb, *vb, *ab, *fb, *sb;
    cudaGetSymbolAddress((void**)&xb,  g_x);
    cudaGetSymbolAddress((void**)&lnb, g_ln);
    cudaGetSymbolAddress((void**)&qb,  g_q);
    cudaGetSymbolAddress((void**)&kb,  g_k);
    cudaGetSymbolAddress((void**)&vb,  g_v);
    cudaGetSymbolAddress((void**)&ab,  g_attn);
    cudaGetSymbolAddress((void**)&fb,  g_ff);
    cudaGetSymbolAddress((void**)&sb,  g_scores);

    // dynamic smem sizes per instantiation
    const int SM_128_128 = (2 * 128 * 36 + 2 * 128 * 36) * 4;        // 73728
    const int SM_128_64N = (2 * 128 * 36 + 2 * 32 * (64 + 4)) * 4;   // 54272
    const int SM_64_128  = (2 * 64 * 36 + 2 * 128 * 36) * 4;         // 55296

    cudaFuncSetAttribute((const void*)gemm_qkv_kernel<128, 128>,
                         cudaFuncAttributeMaxDynamicSharedMemorySize, SM_128_128);
    cudaFuncSetAttribute((const void*)gemm_tc_kernel<0, false, 128, 128>,
                         cudaFuncAttributeMaxDynamicSharedMemorySize, SM_128_128);
    cudaFuncSetAttribute((const void*)gemm_tc_kernel<2, false, 128, 128>,
                         cudaFuncAttributeMaxDynamicSharedMemorySize, SM_128_128);
    cudaFuncSetAttribute((const void*)gemm_tc_kernel<0, true, 128, 64>,
                         cudaFuncAttributeMaxDynamicSharedMemorySize, SM_128_64N);
    cudaFuncSetAttribute((const void*)gemm_tc_kernel<3, false, 64, 128>,
                         cudaFuncAttributeMaxDynamicSharedMemorySize, SM_64_128);

    const size_t attn_elems = (size_t)NLAYER * BB * TT * TT;
    float* attn_out = out + ((size_t)out_size - attn_elems);

    embed_kernel<<<(MT * CC + 255) / 256, 256>>>(x, emb, pos, xb);

    const long long LTT2 = (long long)TT * TT;
    const long long LTC  = (long long)TT * CC;

    for (int l = 0; l < NLAYER; l++) {
        const float* wq = Wq + (size_t)l * CC * CC;
        const float* wk = Wk + (size_t)l * CC * CC;
        const float* wv = Wv + (size_t)l * CC * CC;
        const float* wo = Wo + (size_t)l * CC * CC;
        const float* w1 = W1 + (size_t)l * FF * CC;
        const float* w2 = W2 + (size_t)l * CC * FF;

        ln_kernel<<<MT / 8, 256>>>(xb, ln1g + (size_t)l * CC, ln1b + (size_t)l * CC, lnb);

        // QKV fused: 384 blocks
        dim3 gqkv(CC / 128, MT / 128, 3);
        gemm_qkv_kernel<128, 128><<<gqkv, 256, SM_128_128>>>(
            lnb, wq, wk, wv,
            bq + (size_t)l * CC, bk + (size_t)l * CC, bv + (size_t)l * CC,
            qb, kb, vb);

        // scores: S = Q K^T / 8  (per b,h)  M=T, N=T, K=64
        dim3 gs(TT / 128, TT / 128, BB * NH);
        gemm_tc_kernel<0, false, 128, 128><<<gs, 256, SM_128_128>>>(
            qb, kb, nullptr, nullptr, sb,
            CC, CC, TT, HDIM, 0.125f, NH,
            LTC, 64, LTC, 64, (long long)NH * LTT2, LTT2);

        dim3 gsm(TT, BB);
        softmax_avg_kernel<<<gsm, 256>>>(sb, attn_out + (size_t)l * BB * TT * TT);

        // attnv: O = P V  (per b,h)  M=T, N=64, K=T
        dim3 ga(1, TT / 128, BB * NH);
        gemm_tc_kernel<0, true, 128, 64><<<ga, 256, SM_128_64N>>>(
            sb, vb, nullptr, nullptr, ab,
            TT, CC, CC, TT, 1.f, NH,
            (long long)NH * LTT2, LTT2, LTC, 64, LTC, 64);

        // Wo projection + residual
        dim3 gwo(CC / 128, MT / 64, 1);
        gemm_tc_kernel<3, false, 64, 128><<<gwo, 256, SM_64_128>>>(
            ab, wo, bo + (size_t)l * CC, xb, xb,
            CC, CC, CC, CC, 1.f, 1, 0, 0, 0, 0, 0, 0);

        ln_kernel<<<MT / 8, 256>>>(xb, ln2g + (size_t)l * CC, ln2b + (size_t)l * CC, lnb);

        // FFN1 + relu
        dim3 gf1(FF / 128, MT / 128, 1);
        gemm_tc_kernel<2, false, 128, 128><<<gf1, 256, SM_128_128>>>(
            lnb, w1, b1 + (size_t)l * FF, nullptr, fb,
            CC, CC, FF, CC, 1.f, 1, 0, 0, 0, 0, 0, 0);

        // FFN2 + residual
        dim3 gf2(CC / 128, MT / 64, 1);
        gemm_tc_kernel<3, false, 64, 128><<<gf2, 256, SM_64_128>>>(
            fb, w2, b2 + (size_t)l * CC, xb, xb,
            FF, FF, CC, FF, 1.f, 1, 0, 0, 0, 0, 0, 0);
    }

    ln_kernel<<<MT / 8, 256>>>(xb, lnfg, lnfb, lnb);
    final_mean_kernel<<<BB * CC, 256>>>(lnb, out);
}

// round 5
// speedup vs baseline: 4.1520x; 1.0430x over previous
#include <cuda_runtime.h>
#include <math.h>
#include <stdint.h>

#define NLAYER 4
#define BB 2
#define TT 2048
#define CC 512
#define NH 8
#define HDIM 64
#define FF 2048
#define VOCAB 32000
#define MT (BB*TT)   // 4096 rows

// ---------------- scratch (device globals; no allocations allowed) ----------
__device__ float g_x   [(size_t)MT*CC];
__device__ float g_ln  [(size_t)MT*CC];
__device__ float g_q   [(size_t)MT*CC];
__device__ float g_k   [(size_t)MT*CC];
__device__ float g_v   [(size_t)MT*CC];
__device__ float g_attn[(size_t)MT*CC];
__device__ float g_ff  [(size_t)MT*FF];
__device__ float2 g_stats[(size_t)BB*NH*TT];   // per-row (m, l) from flash pass

// ---------------- helpers ----------------------------------------------------
__device__ __forceinline__ uint32_t f2tf32(float x) {
    uint32_t u;
    asm("cvt.rna.tf32.f32 %0, %1;" : "=r"(u) : "f"(x));
    return u;
}

__device__ __forceinline__ void mma_tf32(float* c, const uint32_t* a, const uint32_t* b) {
    asm volatile(
        "mma.sync.aligned.m16n8k8.row.col.f32.tf32.tf32.f32 "
        "{%0,%1,%2,%3}, {%4,%5,%6,%7}, {%8,%9}, {%0,%1,%2,%3};"
        : "+f"(c[0]), "+f"(c[1]), "+f"(c[2]), "+f"(c[3])
        : "r"(a[0]), "r"(a[1]), "r"(a[2]), "r"(a[3]), "r"(b[0]), "r"(b[1]));
}

__device__ __forceinline__ void cp16(void* sdst, const void* gsrc) {
    unsigned s = (unsigned)__cvta_generic_to_shared(sdst);
    asm volatile("cp.async.cg.shared.global [%0], [%1], 16;\n" :: "r"(s), "l"(gsrc));
}
__device__ __forceinline__ void cp_commit() { asm volatile("cp.async.commit_group;\n"); }
template<int N>
__device__ __forceinline__ void cp_wait() { asm volatile("cp.async.wait_group %0;\n" :: "n"(N)); }

// =============================================================================
// TF32 tensor-core GEMM core (NT). C[M,N] = A[M,K] @ W[N,K]^T
// CTA tile BM x BN x 32, 256 threads, double-buffered cp.async pipeline.
// EPI: 1 = +bias, 2 = +bias,relu, 3 = +bias,+residual
// =============================================================================
template<int EPI, int BM, int BN>
__device__ __forceinline__ void gemm_core(
    const float* __restrict__ A, const float* __restrict__ B,
    const float* __restrict__ bias, const float* __restrict__ res,
    float* __restrict__ C, int lda, int ldb, int ldc, int K)
{
    constexpr int WM   = BM / 64;
    constexpr int WN   = 8 / WM;
    constexpr int NCW  = BN / WN;
    constexpr int NT_  = NCW / 8;

    extern __shared__ float smem[];
    float* As = smem;                        // 2 * BM * 36
    float* Bs = smem + 2 * BM * 36;          // 2 * BN * 36

    const int tid  = threadIdx.x;
    const int lane = tid & 31, wid = tid >> 5;
    const int warpM = (WM == 1) ? 0 : (wid & 1);
    const int warpN = (WM == 1) ? wid : (wid >> 1);
    const int grp = lane >> 2, qd = lane & 3;

    const int row0 = blockIdx.y * BM;
    const int col0 = blockIdx.x * BN;

    float acc[4][NT_][4];
#pragma unroll
    for (int mt = 0; mt < 4; mt++)
#pragma unroll
        for (int nt = 0; nt < NT_; nt++)
#pragma unroll
            for (int i = 0; i < 4; i++) acc[mt][nt][i] = 0.f;

    auto loadA = [&](int buf, int k0) {
#pragma unroll
        for (int i = 0; i < BM / 32; i++) {
            int idx = i * 256 + tid;
            int r = idx >> 3, c4 = (idx & 7) << 2;
            cp16(As + buf * BM * 36 + r * 36 + c4,
                 A + (size_t)(row0 + r) * lda + k0 + c4);
        }
    };
    auto loadB = [&](int buf, int k0) {
#pragma unroll
        for (int i = 0; i < BN / 32; i++) {
            int idx = i * 256 + tid;
            int r = idx >> 3, c4 = (idx & 7) << 2;
            cp16(Bs + buf * BN * 36 + r * 36 + c4,
                 B + (size_t)(col0 + r) * ldb + k0 + c4);
        }
    };

    auto compute = [&](int buf) {
        const float* Ab = As + buf * BM * 36;
        const float* Bb = Bs + buf * BN * 36;
#pragma unroll
        for (int kt = 0; kt < 4; kt++) {
            uint32_t af[4][4];
#pragma unroll
            for (int mt = 0; mt < 4; mt++) {
                int r0 = warpM * 64 + mt * 16 + grp;
                af[mt][0] = f2tf32(Ab[(r0)     * 36 + kt * 8 + qd]);
                af[mt][1] = f2tf32(Ab[(r0 + 8) * 36 + kt * 8 + qd]);
                af[mt][2] = f2tf32(Ab[(r0)     * 36 + kt * 8 + qd + 4]);
                af[mt][3] = f2tf32(Ab[(r0 + 8) * 36 + kt * 8 + qd + 4]);
            }
            uint32_t bf[NT_][2];
#pragma unroll
            for (int nt = 0; nt < NT_; nt++) {
                int nb = warpN * NCW + nt * 8 + grp;
                bf[nt][0] = f2tf32(Bb[nb * 36 + kt * 8 + qd]);
                bf[nt][1] = f2tf32(Bb[nb * 36 + kt * 8 + qd + 4]);
            }
#pragma unroll
            for (int mt = 0; mt < 4; mt++)
#pragma unroll
                for (int nt = 0; nt < NT_; nt++)
                    mma_tf32(acc[mt][nt], af[mt], bf[nt]);
        }
    };

    const int nk = K >> 5;
    loadA(0, 0);  loadB(0, 0);  cp_commit();
    loadA(1, 32); loadB(1, 32); cp_commit();
    cp_wait<1>();
    __syncthreads();

    for (int kb = 0; kb < nk; kb++) {
        compute(kb & 1);
        __syncthreads();
        if (kb + 2 < nk) { loadA(kb & 1, (kb + 2) * 32); loadB(kb & 1, (kb + 2) * 32); }
        cp_commit();
        cp_wait<1>();
        __syncthreads();
    }

#pragma unroll
    for (int mt = 0; mt < 4; mt++)
#pragma unroll
        for (int nt = 0; nt < NT_; nt++) {
            int row = row0 + warpM * 64 + mt * 16 + grp;
            int col = col0 + warpN * NCW + nt * 8 + qd * 2;
#pragma unroll
            for (int half = 0; half < 2; half++) {
                int r = row + half * 8;
                float v0 = acc[mt][nt][half * 2 + 0];
                float v1 = acc[mt][nt][half * 2 + 1];
                v0 += bias[col]; v1 += bias[col + 1];
                if (EPI == 2) { v0 = fmaxf(v0, 0.f); v1 = fmaxf(v1, 0.f); }
                if (EPI == 3) {
                    v0 += res[(size_t)r * ldc + col];
                    v1 += res[(size_t)r * ldc + col + 1];
                }
                *(float2*)(C + (size_t)r * ldc + col) = make_float2(v0, v1);
            }
        }
}

template<int EPI, int BM, int BN>
__global__ void __launch_bounds__(256)
gemm_tc_kernel(const float* __restrict__ A, const float* __restrict__ B,
               const float* __restrict__ bias, const float* __restrict__ res,
               float* __restrict__ C, int lda, int ldb, int ldc, int K) {
    gemm_core<EPI, BM, BN>(A, B, bias, res, C, lda, ldb, ldc, K);
}

// ---- fused QKV (z selects weight/bias/output) --------------------------------
template<int BM, int BN>
__global__ void __launch_bounds__(256)
gemm_qkv_kernel(const float* __restrict__ A,
                const float* __restrict__ Wq, const float* __restrict__ Wk,
                const float* __restrict__ Wv,
                const float* __restrict__ bq, const float* __restrict__ bk,
                const float* __restrict__ bv,
                float* __restrict__ q, float* __restrict__ k, float* __restrict__ v) {
    int z = blockIdx.z;
    const float* B    = z == 0 ? Wq : (z == 1 ? Wk : Wv);
    const float* bias = z == 0 ? bq : (z == 1 ? bk : bv);
    float* C          = z == 0 ? q  : (z == 1 ? k  : v);
    gemm_core<1, BM, BN>(A, B, bias, nullptr, C, CC, CC, CC, CC);
}

// =============================================================================
// Flash attention pass 1: per (qtile=128, h, b): O = softmax(QK^T/8) V (online),
// writes O into [B,T,C] layout and per-row stats (m,l).
// 256 threads = 8 warps; warp w owns rows w*16..w*16+15.
// =============================================================================
__global__ void __launch_bounds__(256)
flash_kernel(const float* __restrict__ q, const float* __restrict__ k,
             const float* __restrict__ v, float* __restrict__ o) {
    constexpr int PQ = 68;   // pad for Q/K/P (stride % 32 == 4)
    constexpr int PV = 72;   // pad for V    (stride % 32 == 8)
    extern __shared__ float sm[];
    float* Qs = sm;                          // 128*68
    float* Ks = Qs + 128 * PQ;               // 2 * 64*68
    float* Vs = Ks + 2 * 64 * PQ;            // 2 * 64*72
    float* Ps = Vs + 2 * 64 * PV;            // 128*68

    const int qt = blockIdx.x, h = blockIdx.y, b = blockIdx.z;
    const int tid = threadIdx.x, lane = tid & 31, w = tid >> 5;
    const int grp = lane >> 2, qd = lane & 3;
    const int rbase = w * 16;

    const float* Qp = q + ((size_t)(b * TT) + qt * 128) * CC + h * 64;
    const float* Kp = k + (size_t)b * TT * CC + h * 64;
    const float* Vp = v + (size_t)b * TT * CC + h * 64;

    // stage Q, pre-scaled by 1/8 (exact power of 2)
#pragma unroll
    for (int i = 0; i < 8; i++) {
        int j = i * 256 + tid;
        int r = j >> 4, c4 = (j & 15) << 2;
        float4 t4 = *(const float4*)(Qp + (size_t)r * CC + c4);
        Qs[r * PQ + c4 + 0] = t4.x * 0.125f;
        Qs[r * PQ + c4 + 1] = t4.y * 0.125f;
        Qs[r * PQ + c4 + 2] = t4.z * 0.125f;
        Qs[r * PQ + c4 + 3] = t4.w * 0.125f;
    }

    auto loadKV = [&](int buf, int kt) {
        const float* Kt = Kp + (size_t)kt * 64 * CC;
        const float* Vt = Vp + (size_t)kt * 64 * CC;
#pragma unroll
        for (int i = 0; i < 4; i++) {
            int j = i * 256 + tid;
            int r = j >> 4, c4 = (j & 15) << 2;
            cp16(Ks + buf * 64 * PQ + r * PQ + c4, Kt + (size_t)r * CC + c4);
            cp16(Vs + buf * 64 * PV + r * PV + c4, Vt + (size_t)r * CC + c4);
        }
    };
    loadKV(0, 0); cp_commit();
    loadKV(1, 1); cp_commit();

    float oacc[8][4];
#pragma unroll
    for (int nt = 0; nt < 8; nt++)
#pragma unroll
        for (int i = 0; i < 4; i++) oacc[nt][i] = 0.f;
    float m0 = -1e30f, m1 = -1e30f, l0 = 0.f, l1 = 0.f;

    for (int kt = 0; kt < 32; kt++) {
        cp_wait<1>(); __syncthreads();
        const float* Kb = Ks + (kt & 1) * 64 * PQ;
        const float* Vb = Vs + (kt & 1) * 64 * PV;

        // ---- S = Qs @ Kb^T  (warp rows rbase..rbase+15, 64 keys) ----
        float sacc[8][4];
#pragma unroll
        for (int nt = 0; nt < 8; nt++)
#pragma unroll
            for (int i = 0; i < 4; i++) sacc[nt][i] = 0.f;
#pragma unroll
        for (int k8 = 0; k8 < 8; k8++) {
            uint32_t af[4];
            af[0] = f2tf32(Qs[(rbase + grp)     * PQ + k8 * 8 + qd]);
            af[1] = f2tf32(Qs[(rbase + grp + 8) * PQ + k8 * 8 + qd]);
            af[2] = f2tf32(Qs[(rbase + grp)     * PQ + k8 * 8 + qd + 4]);
            af[3] = f2tf32(Qs[(rbase + grp + 8) * PQ + k8 * 8 + qd + 4]);
#pragma unroll
            for (int nt = 0; nt < 8; nt++) {
                uint32_t bf[2];
                bf[0] = f2tf32(Kb[(nt * 8 + grp) * PQ + k8 * 8 + qd]);
                bf[1] = f2tf32(Kb[(nt * 8 + grp) * PQ + k8 * 8 + qd + 4]);
                mma_tf32(sacc[nt], af, bf);
            }
        }

        // ---- online softmax update ----
        float mx0 = -1e30f, mx1 = -1e30f;
#pragma unroll
        for (int nt = 0; nt < 8; nt++) {
            mx0 = fmaxf(mx0, fmaxf(sacc[nt][0], sacc[nt][1]));
            mx1 = fmaxf(mx1, fmaxf(sacc[nt][2], sacc[nt][3]));
        }
        mx0 = fmaxf(mx0, __shfl_xor_sync(0xffffffffu, mx0, 1));
        mx0 = fmaxf(mx0, __shfl_xor_sync(0xffffffffu, mx0, 2));
        mx1 = fmaxf(mx1, __shfl_xor_sync(0xffffffffu, mx1, 1));
        mx1 = fmaxf(mx1, __shfl_xor_sync(0xffffffffu, mx1, 2));
        float mn0 = fmaxf(m0, mx0), mn1 = fmaxf(m1, mx1);
        float f0 = __expf(m0 - mn0), f1 = __expf(m1 - mn1);
        m0 = mn0; m1 = mn1;
        float rs0 = 0.f, rs1 = 0.f;
#pragma unroll
        for (int nt = 0; nt < 8; nt++) {
            sacc[nt][0] = __expf(sacc[nt][0] - m0);
            sacc[nt][1] = __expf(sacc[nt][1] - m0);
            sacc[nt][2] = __expf(sacc[nt][2] - m1);
            sacc[nt][3] = __expf(sacc[nt][3] - m1);
            rs0 += sacc[nt][0] + sacc[nt][1];
            rs1 += sacc[nt][2] + sacc[nt][3];
        }
        rs0 += __shfl_xor_sync(0xffffffffu, rs0, 1);
        rs0 += __shfl_xor_sync(0xffffffffu, rs0, 2);
        rs1 += __shfl_xor_sync(0xffffffffu, rs1, 1);
        rs1 += __shfl_xor_sync(0xffffffffu, rs1, 2);
        l0 = l0 * f0 + rs0;
        l1 = l1 * f1 + rs1;
#pragma unroll
        for (int nt = 0; nt < 8; nt++) {
            oacc[nt][0] *= f0; oacc[nt][1] *= f0;
            oacc[nt][2] *= f1; oacc[nt][3] *= f1;
        }

        // ---- stage P (warp-private rows) ----
#pragma unroll
        for (int nt = 0; nt < 8; nt++) {
            Ps[(rbase + grp)     * PQ + nt * 8 + qd * 2]     = sacc[nt][0];
            Ps[(rbase + grp)     * PQ + nt * 8 + qd * 2 + 1] = sacc[nt][1];
            Ps[(rbase + grp + 8) * PQ + nt * 8 + qd * 2]     = sacc[nt][2];
            Ps[(rbase + grp + 8) * PQ + nt * 8 + qd * 2 + 1] = sacc[nt][3];
        }
        __syncwarp();

        // ---- O += P @ V ----
#pragma unroll
        for (int k8 = 0; k8 < 8; k8++) {
            uint32_t af[4];
            af[0] = f2tf32(Ps[(rbase + grp)     * PQ + k8 * 8 + qd]);
            af[1] = f2tf32(Ps[(rbase + grp + 8) * PQ + k8 * 8 + qd]);
            af[2] = f2tf32(Ps[(rbase + grp)     * PQ + k8 * 8 + qd + 4]);
            af[3] = f2tf32(Ps[(rbase + grp + 8) * PQ + k8 * 8 + qd + 4]);
#pragma unroll
            for (int nt = 0; nt < 8; nt++) {
                uint32_t bf[2];
                bf[0] = f2tf32(Vb[(k8 * 8 + qd)     * PV + nt * 8 + grp]);
                bf[1] = f2tf32(Vb[(k8 * 8 + qd + 4) * PV + nt * 8 + grp]);
                mma_tf32(oacc[nt], af, bf);
            }
        }
        __syncthreads();
        if (kt + 2 < 32) loadKV(kt & 1, kt + 2);
        cp_commit();
    }

    // ---- epilogue: normalize + write O and stats ----
    float i0 = 1.f / l0, i1 = 1.f / l1;
    int row0 = qt * 128 + rbase + grp;
    float* Op = o + ((size_t)(b * TT) + row0) * CC + h * 64;
#pragma unroll
    for (int nt = 0; nt < 8; nt++) {
        *(float2*)(Op + nt * 8 + qd * 2) =
            make_float2(oacc[nt][0] * i0, oacc[nt][1] * i0);
        *(float2*)(Op + (size_t)8 * CC + nt * 8 + qd * 2) =
            make_float2(oacc[nt][2] * i1, oacc[nt][3] * i1);
    }
    if (qd == 0) {
        g_stats[(size_t)(b * NH + h) * TT + row0]     = make_float2(m0, l0);
        g_stats[(size_t)(b * NH + h) * TT + row0 + 8] = make_float2(m1, l1);
    }
}

// =============================================================================
// Pass 2: head-averaged attention map. Per (kchunk=128, qtile=128, b) CTA:
// recompute S per head, p = exp(s/8 - m)/l, accumulate over 8 heads, write avg.
// 8 warps: warpM = w>>1 (32 rows), warpN = w&1 (64 cols).
// =============================================================================
__global__ void __launch_bounds__(256)
avgmap_kernel(const float* __restrict__ q, const float* __restrict__ k,
              float* __restrict__ avg) {
    constexpr int PQ = 68;
    extern __shared__ float sm[];
    float* Qs = sm;                       // 2 * 128*68
    float* Ks = Qs + 2 * 128 * PQ;        // 2 * 128*68
    float2* St = (float2*)(Ks + 2 * 128 * PQ);  // [8][128]

    const int kc = blockIdx.x, qt = blockIdx.y, b = blockIdx.z;
    const int tid = threadIdx.x, lane = tid & 31, w = tid >> 5;
    const int grp = lane >> 2, qd = lane & 3;
    const int wm = w >> 1, wn = w & 1;

    for (int j = tid; j < NH * 128; j += 256) {
        int h = j >> 7, r = j & 127;
        St[j] = g_stats[(size_t)(b * NH + h) * TT + qt * 128 + r];
    }

    auto loadQK = [&](int buf, int h) {
        const float* Qp = q + ((size_t)(b * TT) + qt * 128) * CC + h * 64;
        const float* Kp = k + ((size_t)(b * TT) + kc * 128) * CC + h * 64;
#pragma unroll
        for (int i = 0; i < 8; i++) {
            int j = i * 256 + tid;
            int r = j >> 4, c4 = (j & 15) << 2;
            cp16(Qs + buf * 128 * PQ + r * PQ + c4, Qp + (size_t)r * CC + c4);
            cp16(Ks + buf * 128 * PQ + r * PQ + c4, Kp + (size_t)r * CC + c4);
        }
    };
    loadQK(0, 0); cp_commit();

    float aacc[2][8][4];
#pragma unroll
    for (int mt = 0; mt < 2; mt++)
#pragma unroll
        for (int nt = 0; nt < 8; nt++)
#pragma unroll
            for (int i = 0; i < 4; i++) aacc[mt][nt][i] = 0.f;

    for (int h = 0; h < NH; h++) {
        if (h + 1 < NH) loadQK((h + 1) & 1, h + 1);
        cp_commit();
        cp_wait<1>(); __syncthreads();
        const float* Qb = Qs + (h & 1) * 128 * PQ;
        const float* Kb = Ks + (h & 1) * 128 * PQ;

        float sacc[2][8][4];
#pragma unroll
        for (int mt = 0; mt < 2; mt++)
#pragma unroll
            for (int nt = 0; nt < 8; nt++)
#pragma unroll
                for (int i = 0; i < 4; i++) sacc[mt][nt][i] = 0.f;

#pragma unroll
        for (int k8 = 0; k8 < 8; k8++) {
            uint32_t af[2][4];
#pragma unroll
            for (int mt = 0; mt < 2; mt++) {
                int r0 = wm * 32 + mt * 16 + grp;
                af[mt][0] = f2tf32(Qb[(r0)     * PQ + k8 * 8 + qd]);
                af[mt][1] = f2tf32(Qb[(r0 + 8) * PQ + k8 * 8 + qd]);
                af[mt][2] = f2tf32(Qb[(r0)     * PQ + k8 * 8 + qd + 4]);
                af[mt][3] = f2tf32(Qb[(r0 + 8) * PQ + k8 * 8 + qd + 4]);
            }
#pragma unroll
            for (int nt = 0; nt < 8; nt++) {
                int nb = wn * 64 + nt * 8 + grp;
                uint32_t bf[2];
                bf[0] = f2tf32(Kb[nb * PQ + k8 * 8 + qd]);
                bf[1] = f2tf32(Kb[nb * PQ + k8 * 8 + qd + 4]);
#pragma unroll
                for (int mt = 0; mt < 2; mt++)
                    mma_tf32(sacc[mt][nt], af[mt], bf);
            }
        }

        // p = exp(s/8 - m) / l, accumulate
#pragma unroll
        for (int mt = 0; mt < 2; mt++) {
            int r0 = wm * 32 + mt * 16 + grp;
            float2 s0 = St[h * 128 + r0];
            float2 s1 = St[h * 128 + r0 + 8];
            float il0 = 1.f / s0.y, il1 = 1.f / s1.y;
#pragma unroll
            for (int nt = 0; nt < 8; nt++) {
                aacc[mt][nt][0] += __expf(0.125f * sacc[mt][nt][0] - s0.x) * il0;
                aacc[mt][nt][1] += __expf(0.125f * sacc[mt][nt][1] - s0.x) * il0;
                aacc[mt][nt][2] += __expf(0.125f * sacc[mt][nt][2] - s1.x) * il1;
                aacc[mt][nt][3] += __expf(0.125f * sacc[mt][nt][3] - s1.x) * il1;
            }
        }
        __syncthreads();
    }

    const float inv8 = 1.0f / NH;
#pragma unroll
    for (int mt = 0; mt < 2; mt++) {
        int qrow = qt * 128 + wm * 32 + mt * 16 + grp;
        int kcol = kc * 128 + wn * 64;
        float* A0 = avg + ((size_t)(b * TT) + qrow) * TT + kcol;
        float* A1 = A0 + (size_t)8 * TT;
#pragma unroll
        for (int nt = 0; nt < 8; nt++) {
            *(float2*)(A0 + nt * 8 + qd * 2) =
                make_float2(aacc[mt][nt][0] * inv8, aacc[mt][nt][1] * inv8);
            *(float2*)(A1 + nt * 8 + qd * 2) =
                make_float2(aacc[mt][nt][2] * inv8, aacc[mt][nt][3] * inv8);
        }
    }
}

// ---------------- embedding + positional ------------------------------------
__global__ void embed_kernel(const int* __restrict__ x,
                             const float* __restrict__ emb,
                             const float* __restrict__ pos,
                             float* __restrict__ out) {
    int idx = blockIdx.x * blockDim.x + threadIdx.x;
    if (idx >= MT * CC) return;
    int c  = idx % CC;
    int bt = idx / CC;
    int t  = bt % TT;
    int tok = x[bt];
    if (tok < 0) tok = 0;
    if (tok >= VOCAB) tok = VOCAB - 1;
    out[idx] = emb[(size_t)tok * CC + c] + pos[(size_t)t * CC + c];
}

// ---------------- layernorm: one warp per 512-float row ----------------------
__global__ void ln_kernel(const float* __restrict__ in,
                          const float* __restrict__ g,
                          const float* __restrict__ b,
                          float* __restrict__ out) {
    int row  = blockIdx.x * 8 + (threadIdx.x >> 5);
    int lane = threadIdx.x & 31;
    const float4* xr = (const float4*)(in + (size_t)row * CC);
    float4 v[4];
    float s = 0.f;
#pragma unroll
    for (int i = 0; i < 4; i++) {
        v[i] = xr[i * 32 + lane];
        s += v[i].x + v[i].y + v[i].z + v[i].w;
    }
#pragma unroll
    for (int o = 16; o; o >>= 1) s += __shfl_xor_sync(0xffffffffu, s, o);
    float mean = s * (1.0f / CC);
    float var = 0.f;
#pragma unroll
    for (int i = 0; i < 4; i++) {
        float dx = v[i].x - mean, dy = v[i].y - mean, dz = v[i].z - mean, dw = v[i].w - mean;
        var += dx * dx + dy * dy + dz * dz + dw * dw;
    }
#pragma unroll
    for (int o = 16; o; o >>= 1) var += __shfl_xor_sync(0xffffffffu, var, o);
    float rstd = rsqrtf(var * (1.0f / CC) + 1e-5f);
    float4* op = (float4*)(out + (size_t)row * CC);
    const float4* gp = (const float4*)g;
    const float4* bp = (const float4*)b;
#pragma unroll
    for (int i = 0; i < 4; i++) {
        float4 gg = gp[i * 32 + lane], bb = bp[i * 32 + lane];
        float4 o4;
        o4.x = (v[i].x - mean) * rstd * gg.x + bb.x;
        o4.y = (v[i].y - mean) * rstd * gg.y + bb.y;
        o4.z = (v[i].z - mean) * rstd * gg.z + bb.z;
        o4.w = (v[i].w - mean) * rstd * gg.w + bb.w;
        op[i * 32 + lane] = o4;
    }
}

// ---------------- final pooled output: mean over T of lnf(x) ----------------
__global__ void final_mean_kernel(const float* __restrict__ hln,
                                  float* __restrict__ out) {
    int bd = blockIdx.x;
    int b = bd / CC, d = bd % CC;
    __shared__ float red[256];
    int tid = threadIdx.x;
    float s = 0.f;
    for (int t = tid; t < TT; t += 256)
        s += hln[((size_t)b * TT + t) * CC + d];
    red[tid] = s; __syncthreads();
    for (int o = 128; o > 0; o >>= 1) { if (tid < o) red[tid] += red[tid + o]; __syncthreads(); }
    if (tid == 0) out[bd] = red[0] * (1.0f / TT);
}

// ---------------- launch ------------------------------------------------------
extern "C" void kernel_launch(void* const* d_in, const int* in_sizes, int n_in,
                              void* d_out, int out_size) {
    const int* x      = (const int*)d_in[0];
    const float* emb  = (const float*)d_in[1];
    const float* pos  = (const float*)d_in[2];
    const float* Wq = (const float*)d_in[3],  *bq = (const float*)d_in[4];
    const float* Wk = (const float*)d_in[5],  *bk = (const float*)d_in[6];
    const float* Wv = (const float*)d_in[7],  *bv = (const float*)d_in[8];
    const float* Wo = (const float*)d_in[9],  *bo = (const float*)d_in[10];
    const float* W1 = (const float*)d_in[11], *b1 = (const float*)d_in[12];
    const float* W2 = (const float*)d_in[13], *b2 = (const float*)d_in[14];
    const float* ln1g = (const float*)d_in[15], *ln1b = (const float*)d_in[16];
    const float* ln2g = (const float*)d_in[17], *ln2b = (const float*)d_in[18];
    const float* lnfg = (const float*)d_in[19], *lnfb = (const float*)d_in[20];
    float* out = (float*)d_out;

    float *xb, *lnb, *qb, *kb, *vb, *ab, *fb;
    cudaGetSymbolAddress((void**)&xb,  g_x);
    cudaGetSymbolAddress((void**)&lnb, g_ln);
    cudaGetSymbolAddress((void**)&qb,  g_q);
    cudaGetSymbolAddress((void**)&kb,  g_k);
    cudaGetSymbolAddress((void**)&vb,  g_v);
    cudaGetSymbolAddress((void**)&ab,  g_attn);
    cudaGetSymbolAddress((void**)&fb,  g_ff);

    const int SM_128_128 = (2 * 128 * 36 + 2 * 128 * 36) * 4;      // 73728
    const int SM_64_128  = (2 * 64 * 36 + 2 * 128 * 36) * 4;       // 55296
    const int SM_FLASH   = (128 * 68 + 2 * 64 * 68 + 2 * 64 * 72 + 128 * 68) * 4; // 141312
    const int SM_AVG     = (2 * 128 * 68 + 2 * 128 * 68) * 4 + NH * 128 * 8;      // 147456

    cudaFuncSetAttribute((const void*)gemm_qkv_kernel<128, 128>,
                         cudaFuncAttributeMaxDynamicSharedMemorySize, SM_128_128);
    cudaFuncSetAttribute((const void*)gemm_tc_kernel<2, 128, 128>,
                         cudaFuncAttributeMaxDynamicSharedMemorySize, SM_128_128);
    cudaFuncSetAttribute((const void*)gemm_tc_kernel<3, 64, 128>,
                         cudaFuncAttributeMaxDynamicSharedMemorySize, SM_64_128);
    cudaFuncSetAttribute((const void*)flash_kernel,
                         cudaFuncAttributeMaxDynamicSharedMemorySize, SM_FLASH);
    cudaFuncSetAttribute((const void*)avgmap_kernel,
                         cudaFuncAttributeMaxDynamicSharedMemorySize, SM_AVG);

    const size_t attn_elems = (size_t)NLAYER * BB * TT * TT;
    float* attn_out = out + ((size_t)out_size - attn_elems);

    embed_kernel<<<(MT * CC + 255) / 256, 256>>>(x, emb, pos, xb);

    for (int l = 0; l < NLAYER; l++) {
        const float* wq = Wq + (size_t)l * CC * CC;
        const float* wk = Wk + (size_t)l * CC * CC;
        const float* wv = Wv + (size_t)l * CC * CC;
        const float* wo = Wo + (size_t)l * CC * CC;
        const float* w1 = W1 + (size_t)l * FF * CC;
        const float* w2 = W2 + (size_t)l * CC * FF;

        ln_kernel<<<MT / 8, 256>>>(xb, ln1g + (size_t)l * CC, ln1b + (size_t)l * CC, lnb);

        dim3 gqkv(CC / 128, MT / 128, 3);
        gemm_qkv_kernel<128, 128><<<gqkv, 256, SM_128_128>>>(
            lnb, wq, wk, wv,
            bq + (size_t)l * CC, bk + (size_t)l * CC, bv + (size_t)l * CC,
            qb, kb, vb);

        // fused flash attention: O + stats
        dim3 gfl(TT / 128, NH, BB);
        flash_kernel<<<gfl, 256, SM_FLASH>>>(qb, kb, vb, ab);

        // head-averaged attention map
        dim3 gav(TT / 128, TT / 128, BB);
        avgmap_kernel<<<gav, 256, SM_AVG>>>(qb, kb, attn_out + (size_t)l * BB * TT * TT);

        // Wo projection + residual
        dim3 gwo(CC / 128, MT / 64, 1);
        gemm_tc_kernel<3, 64, 128><<<gwo, 256, SM_64_128>>>(
            ab, wo, bo + (size_t)l * CC, xb, xb, CC, CC, CC, CC);

        ln_kernel<<<MT / 8, 256>>>(xb, ln2g + (size_t)l * CC, ln2b + (size_t)l * CC, lnb);

        // FFN1 + relu
        dim3 gf1(FF / 128, MT / 128, 1);
        gemm_tc_kernel<2, 128, 128><<<gf1, 256, SM_128_128>>>(
            lnb, w1, b1 + (size_t)l * FF, nullptr, fb, CC, CC, FF, CC);

        // FFN2 + residual
        dim3 gf2(CC / 128, MT / 64, 1);
        gemm_tc_kernel<3, 64, 128><<<gf2, 256, SM_64_128>>>(
            fb, w2, b2 + (size_t)l * CC, xb, xb, FF, FF, CC, FF);
    }

    ln_kernel<<<MT / 8, 256>>>(xb, lnfg, lnfb, lnb);
    final_mean_kernel<<<BB * CC, 256>>>(lnb, out);
}

// round 6
// speedup vs baseline: 4.5450x; 1.0947x over previous
#include <cuda_runtime.h>
#include <math.h>
#include <stdint.h>

#define NLAYER 4
#define BB 2
#define TT 2048
#define CC 512
#define NH 8
#define HDIM 64
#define FF 2048
#define VOCAB 32000
#define MT (BB*TT)   // 4096 rows

// ---------------- scratch (device globals; no allocations allowed) ----------
__device__ float g_x   [(size_t)MT*CC];
__device__ float g_ln  [(size_t)MT*CC];
__device__ float g_q   [(size_t)MT*CC];
__device__ float g_k   [(size_t)MT*CC];
__device__ float g_v   [(size_t)MT*CC];
__device__ float g_attn[(size_t)MT*CC];
__device__ float g_ff  [(size_t)MT*FF];
__device__ float2 g_stats[(size_t)BB*NH*TT];   // per-row (m, l) from flash pass

// ---------------- helpers ----------------------------------------------------
__device__ __forceinline__ uint32_t f2tf32(float x) {
    uint32_t u;
    asm("cvt.rna.tf32.f32 %0, %1;" : "=r"(u) : "f"(x));
    return u;
}

__device__ __forceinline__ void mma_tf32(float* c, const uint32_t* a, const uint32_t* b) {
    asm volatile(
        "mma.sync.aligned.m16n8k8.row.col.f32.tf32.tf32.f32 "
        "{%0,%1,%2,%3}, {%4,%5,%6,%7}, {%8,%9}, {%0,%1,%2,%3};"
        : "+f"(c[0]), "+f"(c[1]), "+f"(c[2]), "+f"(c[3])
        : "r"(a[0]), "r"(a[1]), "r"(a[2]), "r"(a[3]), "r"(b[0]), "r"(b[1]));
}

__device__ __forceinline__ void cp16(void* sdst, const void* gsrc) {
    unsigned s = (unsigned)__cvta_generic_to_shared(sdst);
    asm volatile("cp.async.cg.shared.global [%0], [%1], 16;\n" :: "r"(s), "l"(gsrc));
}
__device__ __forceinline__ void cp_commit() { asm volatile("cp.async.commit_group;\n"); }
template<int N>
__device__ __forceinline__ void cp_wait() { asm volatile("cp.async.wait_group %0;\n" :: "n"(N)); }

// =============================================================================
// TF32 tensor-core GEMM core (NT). C[M,N] = A[M,K] @ W[N,K]^T
// CTA tile BM x BN x 32, 256 threads, double-buffered cp.async pipeline.
// EPI: 1 = +bias, 2 = +bias,relu, 3 = +bias,+residual
// =============================================================================
template<int EPI, int BM, int BN>
__device__ __forceinline__ void gemm_core(
    const float* __restrict__ A, const float* __restrict__ B,
    const float* __restrict__ bias, const float* __restrict__ res,
    float* __restrict__ C, int lda, int ldb, int ldc, int K)
{
    constexpr int WM   = BM / 64;
    constexpr int WN   = 8 / WM;
    constexpr int NCW  = BN / WN;
    constexpr int NT_  = NCW / 8;

    extern __shared__ float smem[];
    float* As = smem;                        // 2 * BM * 36
    float* Bs = smem + 2 * BM * 36;          // 2 * BN * 36

    const int tid  = threadIdx.x;
    const int lane = tid & 31, wid = tid >> 5;
    const int warpM = (WM == 1) ? 0 : (wid & 1);
    const int warpN = (WM == 1) ? wid : (wid >> 1);
    const int grp = lane >> 2, qd = lane & 3;

    const int row0 = blockIdx.y * BM;
    const int col0 = blockIdx.x * BN;

    float acc[4][NT_][4];
#pragma unroll
    for (int mt = 0; mt < 4; mt++)
#pragma unroll
        for (int nt = 0; nt < NT_; nt++)
#pragma unroll
            for (int i = 0; i < 4; i++) acc[mt][nt][i] = 0.f;

    auto loadA = [&](int buf, int k0) {
#pragma unroll
        for (int i = 0; i < BM / 32; i++) {
            int idx = i * 256 + tid;
            int r = idx >> 3, c4 = (idx & 7) << 2;
            cp16(As + buf * BM * 36 + r * 36 + c4,
                 A + (size_t)(row0 + r) * lda + k0 + c4);
        }
    };
    auto loadB = [&](int buf, int k0) {
#pragma unroll
        for (int i = 0; i < BN / 32; i++) {
            int idx = i * 256 + tid;
            int r = idx >> 3, c4 = (idx & 7) << 2;
            cp16(Bs + buf * BN * 36 + r * 36 + c4,
                 B + (size_t)(col0 + r) * ldb + k0 + c4);
        }
    };

    auto compute = [&](int buf) {
        const float* Ab = As + buf * BM * 36;
        const float* Bb = Bs + buf * BN * 36;
#pragma unroll
        for (int kt = 0; kt < 4; kt++) {
            uint32_t af[4][4];
#pragma unroll
            for (int mt = 0; mt < 4; mt++) {
                int r0 = warpM * 64 + mt * 16 + grp;
                af[mt][0] = f2tf32(Ab[(r0)     * 36 + kt * 8 + qd]);
                af[mt][1] = f2tf32(Ab[(r0 + 8) * 36 + kt * 8 + qd]);
                af[mt][2] = f2tf32(Ab[(r0)     * 36 + kt * 8 + qd + 4]);
                af[mt][3] = f2tf32(Ab[(r0 + 8) * 36 + kt * 8 + qd + 4]);
            }
            uint32_t bf[NT_][2];
#pragma unroll
            for (int nt = 0; nt < NT_; nt++) {
                int nb = warpN * NCW + nt * 8 + grp;
                bf[nt][0] = f2tf32(Bb[nb * 36 + kt * 8 + qd]);
                bf[nt][1] = f2tf32(Bb[nb * 36 + kt * 8 + qd + 4]);
            }
#pragma unroll
            for (int mt = 0; mt < 4; mt++)
#pragma unroll
                for (int nt = 0; nt < NT_; nt++)
                    mma_tf32(acc[mt][nt], af[mt], bf[nt]);
        }
    };

    const int nk = K >> 5;
    loadA(0, 0);  loadB(0, 0);  cp_commit();
    loadA(1, 32); loadB(1, 32); cp_commit();
    cp_wait<1>();
    __syncthreads();

    for (int kb = 0; kb < nk; kb++) {
        compute(kb & 1);
        __syncthreads();
        if (kb + 2 < nk) { loadA(kb & 1, (kb + 2) * 32); loadB(kb & 1, (kb + 2) * 32); }
        cp_commit();
        cp_wait<1>();
        __syncthreads();
    }

#pragma unroll
    for (int mt = 0; mt < 4; mt++)
#pragma unroll
        for (int nt = 0; nt < NT_; nt++) {
            int row = row0 + warpM * 64 + mt * 16 + grp;
            int col = col0 + warpN * NCW + nt * 8 + qd * 2;
#pragma unroll
            for (int half = 0; half < 2; half++) {
                int r = row + half * 8;
                float v0 = acc[mt][nt][half * 2 + 0];
                float v1 = acc[mt][nt][half * 2 + 1];
                v0 += bias[col]; v1 += bias[col + 1];
                if (EPI == 2) { v0 = fmaxf(v0, 0.f); v1 = fmaxf(v1, 0.f); }
                if (EPI == 3) {
                    v0 += res[(size_t)r * ldc + col];
                    v1 += res[(size_t)r * ldc + col + 1];
                }
                *(float2*)(C + (size_t)r * ldc + col) = make_float2(v0, v1);
            }
        }
}

template<int EPI, int BM, int BN>
__global__ void __launch_bounds__(256, 2)
gemm_tc_kernel(const float* __restrict__ A, const float* __restrict__ B,
               const float* __restrict__ bias, const float* __restrict__ res,
               float* __restrict__ C, int lda, int ldb, int ldc, int K) {
    gemm_core<EPI, BM, BN>(A, B, bias, res, C, lda, ldb, ldc, K);
}

// ---- fused QKV (z selects weight/bias/output) --------------------------------
template<int BM, int BN>
__global__ void __launch_bounds__(256, 2)
gemm_qkv_kernel(const float* __restrict__ A,
                const float* __restrict__ Wq, const float* __restrict__ Wk,
                const float* __restrict__ Wv,
                const float* __restrict__ bq, const float* __restrict__ bk,
                const float* __restrict__ bv,
                float* __restrict__ q, float* __restrict__ k, float* __restrict__ v) {
    int z = blockIdx.z;
    const float* B    = z == 0 ? Wq : (z == 1 ? Wk : Wv);
    const float* bias = z == 0 ? bq : (z == 1 ? bk : bv);
    float* C          = z == 0 ? q  : (z == 1 ? k  : v);
    gemm_core<1, BM, BN>(A, B, bias, nullptr, C, CC, CC, CC, CC);
}

// =============================================================================
// Flash attention pass 1: per (qtile=128, h, b): O = softmax(QK^T/8) V (online).
// 256 threads = 8 warps; warp w owns rows w*16..w*16+15.
// SMEM tiles hold pre-converted tf32 (cvt once at store, plain LDS in loops).
// Single-buffered K/V (105 KB total) -> 2 CTAs/SM.
// =============================================================================
__global__ void __launch_bounds__(256, 2)
flash_kernel(const float* __restrict__ q, const float* __restrict__ k,
             const float* __restrict__ v, float* __restrict__ o) {
    constexpr int PQ = 68;   // stride % 32 == 4 -> conflict-free
    constexpr int PV = 72;   // stride % 32 == 8 -> conflict-free for V pattern
    extern __shared__ uint32_t usm[];
    uint32_t* Qs = usm;                  // 128*68
    uint32_t* Ks = Qs + 128 * PQ;        // 64*68
    uint32_t* Vs = Ks + 64 * PQ;         // 64*72
    uint32_t* Ps = Vs + 64 * PV;         // 128*68

    const int qt = blockIdx.x, h = blockIdx.y, b = blockIdx.z;
    const int tid = threadIdx.x, lane = tid & 31, w = tid >> 5;
    const int grp = lane >> 2, qd = lane & 3;
    const int rbase = w * 16;

    const float* Qp = q + ((size_t)(b * TT) + qt * 128) * CC + h * 64;
    const float* Kp = k + (size_t)b * TT * CC + h * 64;
    const float* Vp = v + (size_t)b * TT * CC + h * 64;

    // stage Q, pre-scaled by 1/8 (exact), converted to tf32
#pragma unroll
    for (int i = 0; i < 8; i++) {
        int j = i * 256 + tid;
        int r = j >> 4, c4 = (j & 15) << 2;
        float4 t4 = *(const float4*)(Qp + (size_t)r * CC + c4);
        uint4 u;
        u.x = f2tf32(t4.x * 0.125f); u.y = f2tf32(t4.y * 0.125f);
        u.z = f2tf32(t4.z * 0.125f); u.w = f2tf32(t4.w * 0.125f);
        *(uint4*)(Qs + r * PQ + c4) = u;
    }

    float oacc[8][4];
#pragma unroll
    for (int nt = 0; nt < 8; nt++)
#pragma unroll
        for (int i = 0; i < 4; i++) oacc[nt][i] = 0.f;
    float m0 = -1e30f, m1 = -1e30f, l0 = 0.f, l1 = 0.f;

    for (int kt = 0; kt < 32; kt++) {
        __syncthreads();   // previous compute done (also orders Q staging at kt=0)
        {
            const float* Kt = Kp + (size_t)kt * 64 * CC;
            const float* Vt = Vp + (size_t)kt * 64 * CC;
#pragma unroll
            for (int i = 0; i < 4; i++) {
                int j = i * 256 + tid;
                int r = j >> 4, c4 = (j & 15) << 2;
                float4 kv = *(const float4*)(Kt + (size_t)r * CC + c4);
                float4 vv = *(const float4*)(Vt + (size_t)r * CC + c4);
                uint4 ku, vu;
                ku.x = f2tf32(kv.x); ku.y = f2tf32(kv.y);
                ku.z = f2tf32(kv.z); ku.w = f2tf32(kv.w);
                vu.x = f2tf32(vv.x); vu.y = f2tf32(vv.y);
                vu.z = f2tf32(vv.z); vu.w = f2tf32(vv.w);
                *(uint4*)(Ks + r * PQ + c4) = ku;
                *(uint4*)(Vs + r * PV + c4) = vu;
            }
        }
        __syncthreads();

        // ---- S = Qs @ Ks^T  (warp rows rbase..rbase+15, 64 keys) ----
        float sacc[8][4];
#pragma unroll
        for (int nt = 0; nt < 8; nt++)
#pragma unroll
            for (int i = 0; i < 4; i++) sacc[nt][i] = 0.f;
#pragma unroll
        for (int k8 = 0; k8 < 8; k8++) {
            uint32_t af[4];
            af[0] = Qs[(rbase + grp)     * PQ + k8 * 8 + qd];
            af[1] = Qs[(rbase + grp + 8) * PQ + k8 * 8 + qd];
            af[2] = Qs[(rbase + grp)     * PQ + k8 * 8 + qd + 4];
            af[3] = Qs[(rbase + grp + 8) * PQ + k8 * 8 + qd + 4];
#pragma unroll
            for (int nt = 0; nt < 8; nt++) {
                uint32_t bf[2];
                bf[0] = Ks[(nt * 8 + grp) * PQ + k8 * 8 + qd];
                bf[1] = Ks[(nt * 8 + grp) * PQ + k8 * 8 + qd + 4];
                mma_tf32(sacc[nt], af, bf);
            }
        }

        // ---- online softmax update ----
        float mx0 = -1e30f, mx1 = -1e30f;
#pragma unroll
        for (int nt = 0; nt < 8; nt++) {
            mx0 = fmaxf(mx0, fmaxf(sacc[nt][0], sacc[nt][1]));
            mx1 = fmaxf(mx1, fmaxf(sacc[nt][2], sacc[nt][3]));
        }
        mx0 = fmaxf(mx0, __shfl_xor_sync(0xffffffffu, mx0, 1));
        mx0 = fmaxf(mx0, __shfl_xor_sync(0xffffffffu, mx0, 2));
        mx1 = fmaxf(mx1, __shfl_xor_sync(0xffffffffu, mx1, 1));
        mx1 = fmaxf(mx1, __shfl_xor_sync(0xffffffffu, mx1, 2));
        float mn0 = fmaxf(m0, mx0), mn1 = fmaxf(m1, mx1);
        float f0 = __expf(m0 - mn0), f1 = __expf(m1 - mn1);
        m0 = mn0; m1 = mn1;
        float rs0 = 0.f, rs1 = 0.f;
#pragma unroll
        for (int nt = 0; nt < 8; nt++) {
            sacc[nt][0] = __expf(sacc[nt][0] - m0);
            sacc[nt][1] = __expf(sacc[nt][1] - m0);
            sacc[nt][2] = __expf(sacc[nt][2] - m1);
            sacc[nt][3] = __expf(sacc[nt][3] - m1);
            rs0 += sacc[nt][0] + sacc[nt][1];
            rs1 += sacc[nt][2] + sacc[nt][3];
        }
        rs0 += __shfl_xor_sync(0xffffffffu, rs0, 1);
        rs0 += __shfl_xor_sync(0xffffffffu, rs0, 2);
        rs1 += __shfl_xor_sync(0xffffffffu, rs1, 1);
        rs1 += __shfl_xor_sync(0xffffffffu, rs1, 2);
        l0 = l0 * f0 + rs0;
        l1 = l1 * f1 + rs1;
#pragma unroll
        for (int nt = 0; nt < 8; nt++) {
            oacc[nt][0] *= f0; oacc[nt][1] *= f0;
            oacc[nt][2] *= f1; oacc[nt][3] *= f1;
        }

        // ---- stage P (warp-private rows) as tf32 ----
#pragma unroll
        for (int nt = 0; nt < 8; nt++) {
            uint2 p0 = make_uint2(f2tf32(sacc[nt][0]), f2tf32(sacc[nt][1]));
            uint2 p1 = make_uint2(f2tf32(sacc[nt][2]), f2tf32(sacc[nt][3]));
            *(uint2*)(Ps + (rbase + grp)     * PQ + nt * 8 + qd * 2) = p0;
            *(uint2*)(Ps + (rbase + grp + 8) * PQ + nt * 8 + qd * 2) = p1;
        }
        __syncwarp();

        // ---- O += P @ V ----
#pragma unroll
        for (int k8 = 0; k8 < 8; k8++) {
            uint32_t af[4];
            af[0] = Ps[(rbase + grp)     * PQ + k8 * 8 + qd];
            af[1] = Ps[(rbase + grp + 8) * PQ + k8 * 8 + qd];
            af[2] = Ps[(rbase + grp)     * PQ + k8 * 8 + qd + 4];
            af[3] = Ps[(rbase + grp + 8) * PQ + k8 * 8 + qd + 4];
#pragma unroll
            for (int nt = 0; nt < 8; nt++) {
                uint32_t bf[2];
                bf[0] = Vs[(k8 * 8 + qd)     * PV + nt * 8 + grp];
                bf[1] = Vs[(k8 * 8 + qd + 4) * PV + nt * 8 + grp];
                mma_tf32(oacc[nt], af, bf);
            }
        }
    }

    // ---- epilogue: normalize + write O and stats ----
    float i0 = 1.f / l0, i1 = 1.f / l1;
    int row0 = qt * 128 + rbase + grp;
    float* Op = o + ((size_t)(b * TT) + row0) * CC + h * 64;
#pragma unroll
    for (int nt = 0; nt < 8; nt++) {
        *(float2*)(Op + nt * 8 + qd * 2) =
            make_float2(oacc[nt][0] * i0, oacc[nt][1] * i0);
        *(float2*)(Op + (size_t)8 * CC + nt * 8 + qd * 2) =
            make_float2(oacc[nt][2] * i1, oacc[nt][3] * i1);
    }
    if (qd == 0) {
        g_stats[(size_t)(b * NH + h) * TT + row0]     = make_float2(m0, l0);
        g_stats[(size_t)(b * NH + h) * TT + row0 + 8] = make_float2(m1, l1);
    }
}

// =============================================================================
// Pass 2: head-averaged attention map. Per (kc=64-col chunk, qt=128-row tile, b):
// loop heads, recompute S, p = exp(s/8 - m)/l, accumulate, write avg.
// 8 warps: wm = w>>1 (32 rows each), wn = w&1 (32 cols each). 2 CTAs/SM.
// =============================================================================
__global__ void __launch_bounds__(256, 2)
avgmap_kernel(const float* __restrict__ q, const float* __restrict__ k,
              float* __restrict__ avg) {
    constexpr int PQ = 68;
    extern __shared__ uint32_t usm[];
    uint32_t* Qs = usm;                   // 128*68
    uint32_t* Ks = Qs + 128 * PQ;         // 64*68
    float2* St = (float2*)(Ks + 64 * PQ); // [8][128]

    const int kc = blockIdx.x, qt = blockIdx.y, b = blockIdx.z;
    const int tid = threadIdx.x, lane = tid & 31, w = tid >> 5;
    const int grp = lane >> 2, qd = lane & 3;
    const int wm = w >> 1, wn = w & 1;

    for (int j = tid; j < NH * 128; j += 256) {
        int h = j >> 7, r = j & 127;
        St[j] = g_stats[(size_t)(b * NH + h) * TT + qt * 128 + r];
    }

    float aacc[2][4][4];
#pragma unroll
    for (int mt = 0; mt < 2; mt++)
#pragma unroll
        for (int nt = 0; nt < 4; nt++)
#pragma unroll
            for (int i = 0; i < 4; i++) aacc[mt][nt][i] = 0.f;

    for (int h = 0; h < NH; h++) {
        __syncthreads();
        // stage Q[128x64] and K[64x64] for this head, tf32-converted
        {
            const float* Qp = q + ((size_t)(b * TT) + qt * 128) * CC + h * 64;
            const float* Kp = k + ((size_t)(b * TT) + kc * 64) * CC + h * 64;
#pragma unroll
            for (int i = 0; i < 8; i++) {
                int j = i * 256 + tid;
                int r = j >> 4, c4 = (j & 15) << 2;
                float4 t4 = *(const float4*)(Qp + (size_t)r * CC + c4);
                uint4 u;
                u.x = f2tf32(t4.x); u.y = f2tf32(t4.y);
                u.z = f2tf32(t4.z); u.w = f2tf32(t4.w);
                *(uint4*)(Qs + r * PQ + c4) = u;
            }
#pragma unroll
            for (int i = 0; i < 4; i++) {
                int j = i * 256 + tid;
                int r = j >> 4, c4 = (j & 15) << 2;
                float4 t4 = *(const float4*)(Kp + (size_t)r * CC + c4);
                uint4 u;
                u.x = f2tf32(t4.x); u.y = f2tf32(t4.y);
                u.z = f2tf32(t4.z); u.w = f2tf32(t4.w);
                *(uint4*)(Ks + r * PQ + c4) = u;
            }
        }
        __syncthreads();

        float sacc[2][4][4];
#pragma unroll
        for (int mt = 0; mt < 2; mt++)
#pragma unroll
            for (int nt = 0; nt < 4; nt++)
#pragma unroll
                for (int i = 0; i < 4; i++) sacc[mt][nt][i] = 0.f;

#pragma unroll
        for (int k8 = 0; k8 < 8; k8++) {
            uint32_t af[2][4];
#pragma unroll
            for (int mt = 0; mt < 2; mt++) {
                int r0 = wm * 32 + mt * 16 + grp;
                af[mt][0] = Qs[(r0)     * PQ + k8 * 8 + qd];
                af[mt][1] = Qs[(r0 + 8) * PQ + k8 * 8 + qd];
                af[mt][2] = Qs[(r0)     * PQ + k8 * 8 + qd + 4];
                af[mt][3] = Qs[(r0 + 8) * PQ + k8 * 8 + qd + 4];
            }
#pragma unroll
            for (int nt = 0; nt < 4; nt++) {
                int nb = wn * 32 + nt * 8 + grp;
                uint32_t bf[2];
                bf[0] = Ks[nb * PQ + k8 * 8 + qd];
                bf[1] = Ks[nb * PQ + k8 * 8 + qd + 4];
#pragma unroll
                for (int mt = 0; mt < 2; mt++)
                    mma_tf32(sacc[mt][nt], af[mt], bf);
            }
        }

        // p = exp(s/8 - m) / l, accumulate over heads
#pragma unroll
        for (int mt = 0; mt < 2; mt++) {
            int r0 = wm * 32 + mt * 16 + grp;
            float2 s0 = St[h * 128 + r0];
            float2 s1 = St[h * 128 + r0 + 8];
            float il0 = 1.f / s0.y, il1 = 1.f / s1.y;
#pragma unroll
            for (int nt = 0; nt < 4; nt++) {
                aacc[mt][nt][0] += __expf(0.125f * sacc[mt][nt][0] - s0.x) * il0;
                aacc[mt][nt][1] += __expf(0.125f * sacc[mt][nt][1] - s0.x) * il0;
                aacc[mt][nt][2] += __expf(0.125f * sacc[mt][nt][2] - s1.x) * il1;
                aacc[mt][nt][3] += __expf(0.125f * sacc[mt][nt][3] - s1.x) * il1;
            }
        }
    }

    const float inv8 = 1.0f / NH;
#pragma unroll
    for (int mt = 0; mt < 2; mt++) {
        int qrow = qt * 128 + wm * 32 + mt * 16 + grp;
        int kcol = kc * 64 + wn * 32;
        float* A0 = avg + ((size_t)(b * TT) + qrow) * TT + kcol;
        float* A1 = A0 + (size_t)8 * TT;
#pragma unroll
        for (int nt = 0; nt < 4; nt++) {
            *(float2*)(A0 + nt * 8 + qd * 2) =
                make_float2(aacc[mt][nt][0] * inv8, aacc[mt][nt][1] * inv8);
            *(float2*)(A1 + nt * 8 + qd * 2) =
                make_float2(aacc[mt][nt][2] * inv8, aacc[mt][nt][3] * inv8);
        }
    }
}

// ---------------- embedding + positional ------------------------------------
__global__ void embed_kernel(const int* __restrict__ x,
                             const float* __restrict__ emb,
                             const float* __restrict__ pos,
                             float* __restrict__ out) {
    int idx = blockIdx.x * blockDim.x + threadIdx.x;
    if (idx >= MT * CC) return;
    int c  = idx % CC;
    int bt = idx / CC;
    int t  = bt % TT;
    int tok = x[bt];
    if (tok < 0) tok = 0;
    if (tok >= VOCAB) tok = VOCAB - 1;
    out[idx] = emb[(size_t)tok * CC + c] + pos[(size_t)t * CC + c];
}

// ---------------- layernorm: one warp per 512-float row ----------------------
__global__ void ln_kernel(const float* __restrict__ in,
                          const float* __restrict__ g,
                          const float* __restrict__ b,
                          float* __restrict__ out) {
    int row  = blockIdx.x * 8 + (threadIdx.x >> 5);
    int lane = threadIdx.x & 31;
    const float4* xr = (const float4*)(in + (size_t)row * CC);
    float4 v[4];
    float s = 0.f;
#pragma unroll
    for (int i = 0; i < 4; i++) {
        v[i] = xr[i * 32 + lane];
        s += v[i].x + v[i].y + v[i].z + v[i].w;
    }
#pragma unroll
    for (int o = 16; o; o >>= 1) s += __shfl_xor_sync(0xffffffffu, s, o);
    float mean = s * (1.0f / CC);
    float var = 0.f;
#pragma unroll
    for (int i = 0; i < 4; i++) {
        float dx = v[i].x - mean, dy = v[i].y - mean, dz = v[i].z - mean, dw = v[i].w - mean;
        var += dx * dx + dy * dy + dz * dz + dw * dw;
    }
#pragma unroll
    for (int o = 16; o; o >>= 1) var += __shfl_xor_sync(0xffffffffu, var, o);
    float rstd = rsqrtf(var * (1.0f / CC) + 1e-5f);
    float4* op = (float4*)(out + (size_t)row * CC);
    const float4* gp = (const float4*)g;
    const float4* bp = (const float4*)b;
#pragma unroll
    for (int i = 0; i < 4; i++) {
        float4 gg = gp[i * 32 + lane], bb = bp[i * 32 + lane];
        float4 o4;
        o4.x = (v[i].x - mean) * rstd * gg.x + bb.x;
        o4.y = (v[i].y - mean) * rstd * gg.y + bb.y;
        o4.z = (v[i].z - mean) * rstd * gg.z + bb.z;
        o4.w = (v[i].w - mean) * rstd * gg.w + bb.w;
        op[i * 32 + lane] = o4;
    }
}

// ---------------- final pooled output: mean over T of lnf(x) ----------------
__global__ void final_mean_kernel(const float* __restrict__ hln,
                                  float* __restrict__ out) {
    int bd = blockIdx.x;
    int b = bd / CC, d = bd % CC;
    __shared__ float red[256];
    int tid = threadIdx.x;
    float s = 0.f;
    for (int t = tid; t < TT; t += 256)
        s += hln[((size_t)b * TT + t) * CC + d];
    red[tid] = s; __syncthreads();
    for (int o = 128; o > 0; o >>= 1) { if (tid < o) red[tid] += red[tid + o]; __syncthreads(); }
    if (tid == 0) out[bd] = red[0] * (1.0f / TT);
}

// ---------------- launch ------------------------------------------------------
extern "C" void kernel_launch(void* const* d_in, const int* in_sizes, int n_in,
                              void* d_out, int out_size) {
    const int* x      = (const int*)d_in[0];
    const float* emb  = (const float*)d_in[1];
    const float* pos  = (const float*)d_in[2];
    const float* Wq = (const float*)d_in[3],  *bq = (const float*)d_in[4];
    const float* Wk = (const float*)d_in[5],  *bk = (const float*)d_in[6];
    const float* Wv = (const float*)d_in[7],  *bv = (const float*)d_in[8];
    const float* Wo = (const float*)d_in[9],  *bo = (const float*)d_in[10];
    const float* W1 = (const float*)d_in[11], *b1 = (const float*)d_in[12];
    const float* W2 = (const float*)d_in[13], *b2 = (const float*)d_in[14];
    const float* ln1g = (const float*)d_in[15], *ln1b = (const float*)d_in[16];
    const float* ln2g = (const float*)d_in[17], *ln2b = (const float*)d_in[18];
    const float* lnfg = (const float*)d_in[19], *lnfb = (const float*)d_in[20];
    float* out = (float*)d_out;

    float *xb, *lnb, *qb, *kb, *vb, *ab, *fb;
    cudaGetSymbolAddress((void**)&xb,  g_x);
    cudaGetSymbolAddress((void**)&lnb, g_ln);
    cudaGetSymbolAddress((void**)&qb,  g_q);
    cudaGetSymbolAddress((void**)&kb,  g_k);
    cudaGetSymbolAddress((void**)&vb,  g_v);
    cudaGetSymbolAddress((void**)&ab,  g_attn);
    cudaGetSymbolAddress((void**)&fb,  g_ff);

    const int SM_128_128 = (2 * 128 * 36 + 2 * 128 * 36) * 4;                 // 73728
    const int SM_64_128  = (2 * 64 * 36 + 2 * 128 * 36) * 4;                  // 55296
    const int SM_FLASH   = (128 * 68 + 64 * 68 + 64 * 72 + 128 * 68) * 4;     // 105472
    const int SM_AVG     = (128 * 68 + 64 * 68) * 4 + NH * 128 * 8;           // 60416

    cudaFuncSetAttribute((const void*)gemm_qkv_kernel<128, 128>,
                         cudaFuncAttributeMaxDynamicSharedMemorySize, SM_128_128);
    cudaFuncSetAttribute((const void*)gemm_tc_kernel<2, 128, 128>,
                         cudaFuncAttributeMaxDynamicSharedMemorySize, SM_128_128);
    cudaFuncSetAttribute((const void*)gemm_tc_kernel<3, 64, 128>,
                         cudaFuncAttributeMaxDynamicSharedMemorySize, SM_64_128);
    cudaFuncSetAttribute((const void*)flash_kernel,
                         cudaFuncAttributeMaxDynamicSharedMemorySize, SM_FLASH);
    cudaFuncSetAttribute((const void*)avgmap_kernel,
                         cudaFuncAttributeMaxDynamicSharedMemorySize, SM_AVG);

    const size_t attn_elems = (size_t)NLAYER * BB * TT * TT;
    float* attn_out = out + ((size_t)out_size - attn_elems);

    embed_kernel<<<(MT * CC + 255) / 256, 256>>>(x, emb, pos, xb);

    for (int l = 0; l < NLAYER; l++) {
        const float* wq = Wq + (size_t)l * CC * CC;
        const float* wk = Wk + (size_t)l * CC * CC;
        const float* wv = Wv + (size_t)l * CC * CC;
        const float* wo = Wo + (size_t)l * CC * CC;
        const float* w1 = W1 + (size_t)l * FF * CC;
        const float* w2 = W2 + (size_t)l * CC * FF;

        ln_kernel<<<MT / 8, 256>>>(xb, ln1g + (size_t)l * CC, ln1b + (size_t)l * CC, lnb);

        dim3 gqkv(CC / 128, MT / 128, 3);
        gemm_qkv_kernel<128, 128><<<gqkv, 256, SM_128_128>>>(
            lnb, wq, wk, wv,
            bq + (size_t)l * CC, bk + (size_t)l * CC, bv + (size_t)l * CC,
            qb, kb, vb);

        // fused flash attention: O + stats
        dim3 gfl(TT / 128, NH, BB);
        flash_kernel<<<gfl, 256, SM_FLASH>>>(qb, kb, vb, ab);

        // head-averaged attention map
        dim3 gav(TT / 64, TT / 128, BB);
        avgmap_kernel<<<gav, 256, SM_AVG>>>(qb, kb, attn_out + (size_t)l * BB * TT * TT);

        // Wo projection + residual
        dim3 gwo(CC / 128, MT / 64, 1);
        gemm_tc_kernel<3, 64, 128><<<gwo, 256, SM_64_128>>>(
            ab, wo, bo + (size_t)l * CC, xb, xb, CC, CC, CC, CC);

        ln_kernel<<<MT / 8, 256>>>(xb, ln2g + (size_t)l * CC, ln2b + (size_t)l * CC, lnb);

        // FFN1 + relu
        dim3 gf1(FF / 128, MT / 128, 1);
        gemm_tc_kernel<2, 128, 128><<<gf1, 256, SM_128_128>>>(
            lnb, w1, b1 + (size_t)l * FF, nullptr, fb, CC, CC, FF, CC);

        // FFN2 + residual
        dim3 gf2(CC / 128, MT / 64, 1);
        gemm_tc_kernel<3, 64, 128><<<gf2, 256, SM_64_128>>>(
            fb, w2, b2 + (size_t)l * CC, xb, xb, FF, FF, CC, FF);
    }

    ln_kernel<<<MT / 8, 256>>>(xb, lnfg, lnfb, lnb);
    final_mean_kernel<<<BB * CC, 256>>>(lnb, out);
}